// round 4
// baseline (speedup 1.0000x reference)
#include <cuda_runtime.h>

#define Bn 8
#define C_IN 128
#define C_OUT 128
#define K2 9
#define HH 64
#define WW 64
#define HW 4096
#define NOFF 18

// Scratch (no cudaMalloc allowed)
__device__ float g_xt[Bn * HW * C_IN];       // x transposed: [b][y][x][c]
__device__ float g_wT[K2 * C_IN * C_OUT];    // w_conv transposed: [k][cin][o]
__device__ float g_woT[K2 * C_IN * NOFF];    // w_offset transposed: [k][cin][oc]
__device__ float g_off[Bn * NOFF * HW];      // offset conv output: [b][ch][y][x]

// ---------------------------------------------------------------------------
// NCHW -> NHWC transpose of x
// ---------------------------------------------------------------------------
__global__ void transpose_x_kernel(const float* __restrict__ x) {
    __shared__ float tile[32][33];
    int b = blockIdx.z;
    int hw0 = blockIdx.x * 32;
    int c0 = blockIdx.y * 32;
    const float* xb = x + (size_t)b * C_IN * HW;
    #pragma unroll
    for (int i = threadIdx.y; i < 32; i += 8)
        tile[i][threadIdx.x] = xb[(size_t)(c0 + i) * HW + hw0 + threadIdx.x];
    __syncthreads();
    float* xt = g_xt + (size_t)b * HW * C_IN;
    #pragma unroll
    for (int i = threadIdx.y; i < 32; i += 8)
        xt[(size_t)(hw0 + i) * C_IN + c0 + threadIdx.x] = tile[threadIdx.x][i];
}

// ---------------------------------------------------------------------------
// Weight transposes
// ---------------------------------------------------------------------------
__global__ void transpose_w_kernel(const float* __restrict__ wo,
                                   const float* __restrict__ wc) {
    int i = blockIdx.x * 256 + threadIdx.x;
    if (i < K2 * C_IN * C_OUT) {
        int o = i & 127;
        int c = (i >> 7) & 127;
        int k = i >> 14;
        g_wT[i] = wc[(o * 128 + c) * 9 + k];
    }
    if (i < K2 * C_IN * NOFF) {
        int oc = i % 18;
        int rem = i / 18;
        int c = rem & 127;
        int k = rem >> 7;
        g_woT[i] = wo[(oc * 128 + c) * 9 + k];
    }
}

// ---------------------------------------------------------------------------
// Offset conv: 3x3 conv, 18 oc, implicit GEMM. Block = 2 rows (128 px).
// ---------------------------------------------------------------------------
__global__ __launch_bounds__(256) void offset_conv_kernel() {
    __shared__ float a_s[128][33];
    __shared__ float w_s[32][20];

    int b = blockIdx.x >> 5;
    int h0 = (blockIdx.x & 31) * 2;
    int tid = threadIdx.x;
    int pp = tid & 63;
    int g = tid >> 6;

    float acc[2][5] = {};

    for (int tap = 0; tap < 9; tap++) {
        int ky = tap / 3, kx = tap % 3;
        for (int c0 = 0; c0 < 128; c0 += 32) {
            #pragma unroll
            for (int i = 0; i < 16; i++) {
                int idx = tid + 256 * i;
                int c = idx & 31, p = idx >> 5;
                int y = h0 + (p >> 6) + ky - 1;
                int xx = (p & 63) + kx - 1;
                float v = 0.f;
                if ((unsigned)y < 64u && (unsigned)xx < 64u)
                    v = g_xt[(((b * 64 + y) * 64 + xx) << 7) + c0 + c];
                a_s[p][c] = v;
            }
            #pragma unroll
            for (int i = 0; i < 3; i++) {
                int idx = tid + 256 * i;
                if (idx < 640) {
                    int c = idx / 20, oc = idx % 20;
                    w_s[c][oc] = (oc < 18)
                        ? g_woT[(tap * 128 + c0 + c) * 18 + oc] : 0.f;
                }
            }
            __syncthreads();
            #pragma unroll
            for (int c = 0; c < 32; c++) {
                float a0 = a_s[pp][c];
                float a1 = a_s[pp + 64][c];
                #pragma unroll
                for (int j = 0; j < 5; j++) {
                    float wv = w_s[c][g + 4 * j];
                    acc[0][j] += a0 * wv;
                    acc[1][j] += a1 * wv;
                }
            }
            __syncthreads();
        }
    }
    #pragma unroll
    for (int r = 0; r < 2; r++) {
        int p = pp + 64 * r;
        int h = h0 + (p >> 6), w = p & 63;
        #pragma unroll
        for (int j = 0; j < 5; j++) {
            int oc = g + 4 * j;
            if (oc < 18)
                g_off[((b * 18 + oc) * 64 + h) * 64 + w] = acc[r][j];
        }
    }
}

// ---------------------------------------------------------------------------
// Deformable conv: block = 128 pixels x 128 outputs, 256 threads.
// Micro-tile 8 px x 8 out per thread -> 1.0 B LDS per FFMA.
// Grid MUST be Bn * (HW/128) = 256 blocks (b = blockIdx.x >> 5).
// ---------------------------------------------------------------------------
__global__ __launch_bounds__(256, 2) void deform_kernel(float* __restrict__ out) {
    __shared__ float w_s[32][128];    // [cin_chunk][o]
    __shared__ float v_s[128][36];    // [pixel][cin_chunk] (padded)
    __shared__ float cw[4][128];      // per-corner bilinear weights (0 if OOB)
    __shared__ int   coff[4][128];    // per-corner clamped (y*64+x)*128 offsets

    int b = blockIdx.x >> 5;               // 32 blocks per image
    int pix0 = (blockIdx.x & 31) * 128;
    int tid = threadIdx.x;
    int lane = tid & 31;
    int warp = tid >> 5;
    int tx = tid & 15;                     // out group: o = tx*8..tx*8+7
    int ty = tid >> 4;                     // px group:  p = ty*8..ty*8+7

    const float* xb = g_xt + (size_t)b * HW * C_IN;
    float acc[8][8] = {};                  // [out][px]

    for (int k = 0; k < 9; k++) {
        // Per-(pixel, tap) sampling setup (first 4 warps, 1 thread/pixel)
        if (tid < 128) {
            int p = tid;
            int gp = pix0 + p;
            int h = gp >> 6, w = gp & 63;
            float dy = g_off[((b * 18 + 2 * k) * 64 + h) * 64 + w];
            float dx = g_off[((b * 18 + 2 * k + 1) * 64 + h) * 64 + w];
            float py = (float)(h - 1 + k / 3) + dy;
            float px = (float)(w - 1 + k % 3) + dx;
            float y0f = floorf(py), x0f = floorf(px);
            float fy = py - y0f, fx = px - x0f;
            #pragma unroll
            for (int j = 0; j < 4; j++) {
                float yf = y0f + (float)(j >> 1);
                float xf = x0f + (float)(j & 1);
                bool ok = (yf >= 0.f && yf < 64.f && xf >= 0.f && xf < 64.f);
                float wy = (j >> 1) ? fy : 1.f - fy;
                float wx = (j & 1) ? fx : 1.f - fx;
                cw[j][p] = ok ? wy * wx : 0.f;
                int yi = (int)fminf(fmaxf(yf, 0.f), 63.f);
                int xi = (int)fminf(fmaxf(xf, 0.f), 63.f);
                coff[j][p] = ((yi << 6) + xi) << 7;
            }
        }
        __syncthreads();

        for (int c0 = 0; c0 < 128; c0 += 32) {
            // Stage W: 32 cin x 128 o, coalesced (lane = o)
            #pragma unroll
            for (int i = 0; i < 16; i++) {
                int idx = tid + 256 * i;
                int c = idx >> 7, o = idx & 127;
                w_s[c][o] = g_wT[(k * 128 + c0 + c) * 128 + o];
            }
            // Gather: warp handles 16 pixels, lane = cin within chunk.
            // 128B-coalesced corner reads, warp-uniform zero-weight skip.
            #pragma unroll
            for (int i = 0; i < 16; i++) {
                int p = warp * 16 + i;
                float a = 0.f;
                #pragma unroll
                for (int j = 0; j < 4; j++) {
                    float wgt = cw[j][p];
                    if (wgt != 0.f)
                        a += wgt * xb[coff[j][p] + c0 + lane];
                }
                v_s[p][lane] = a;
            }
            __syncthreads();

            // MMA: 8 px x 8 out per thread. Per c4-step (4 cin):
            // 8 w LDS.128 (held in regs) + 8 transient v LDS.128, 256 FFMA.
            #pragma unroll
            for (int c4 = 0; c4 < 8; c4++) {
                float4 w0[4], w1[4];
                #pragma unroll
                for (int cc = 0; cc < 4; cc++) {
                    w0[cc] = *(const float4*)&w_s[c4 * 4 + cc][tx * 8];
                    w1[cc] = *(const float4*)&w_s[c4 * 4 + cc][tx * 8 + 4];
                }
                #pragma unroll
                for (int pp = 0; pp < 8; pp++) {
                    float4 va = *(const float4*)&v_s[ty * 8 + pp][c4 * 4];
                    float vv[4] = {va.x, va.y, va.z, va.w};
                    #pragma unroll
                    for (int cc = 0; cc < 4; cc++) {
                        acc[0][pp] += vv[cc] * w0[cc].x;
                        acc[1][pp] += vv[cc] * w0[cc].y;
                        acc[2][pp] += vv[cc] * w0[cc].z;
                        acc[3][pp] += vv[cc] * w0[cc].w;
                        acc[4][pp] += vv[cc] * w1[cc].x;
                        acc[5][pp] += vv[cc] * w1[cc].y;
                        acc[6][pp] += vv[cc] * w1[cc].z;
                        acc[7][pp] += vv[cc] * w1[cc].w;
                    }
                }
            }
            __syncthreads();
        }
    }

    // Store: 8 consecutive px per thread per out channel -> 2 STG.128 each
    float* ob = out + ((size_t)b * 128) * HW + pix0 + ty * 8;
    #pragma unroll
    for (int oo = 0; oo < 8; oo++) {
        int o = tx * 8 + oo;
        *(float4*)(ob + (size_t)o * HW) =
            make_float4(acc[oo][0], acc[oo][1], acc[oo][2], acc[oo][3]);
        *(float4*)(ob + (size_t)o * HW + 4) =
            make_float4(acc[oo][4], acc[oo][5], acc[oo][6], acc[oo][7]);
    }
}

// ---------------------------------------------------------------------------
extern "C" void kernel_launch(void* const* d_in, const int* in_sizes, int n_in,
                              void* d_out, int out_size) {
    const float* x  = (const float*)d_in[0];
    const float* wo = (const float*)d_in[1];   // w_offset
    const float* wc = (const float*)d_in[2];   // w_conv
    float* out = (float*)d_out;

    dim3 tpb(32, 8);
    transpose_x_kernel<<<dim3(HW / 32, C_IN / 32, Bn), tpb>>>(x);
    transpose_w_kernel<<<(K2 * C_IN * C_OUT + 255) / 256, 256>>>(wo, wc);
    offset_conv_kernel<<<Bn * (HH / 2), 256>>>();
    deform_kernel<<<Bn * (HW / 128), 256>>>(out);   // 256 blocks: b = blk>>5
}

// round 5
// speedup vs baseline: 1.0248x; 1.0248x over previous
#include <cuda_runtime.h>

#define Bn 8
#define C_IN 128
#define C_OUT 128
#define K2 9
#define HH 64
#define WW 64
#define HW 4096
#define NOFF 18

// Scratch (no cudaMalloc allowed)
__device__ float g_xt[Bn * HW * C_IN];       // x transposed: [b][y][x][c]
__device__ float g_wT[K2 * C_IN * C_OUT];    // w_conv transposed: [k][cin][o]
__device__ float g_woT[K2 * C_IN * NOFF];    // w_offset transposed: [k][cin][oc]
__device__ float g_off[Bn * NOFF * HW];      // offset conv output: [b][ch][y][x]

// ---------------------------------------------------------------------------
// NCHW -> NHWC transpose of x
// ---------------------------------------------------------------------------
__global__ void transpose_x_kernel(const float* __restrict__ x) {
    __shared__ float tile[32][33];
    int b = blockIdx.z;
    int hw0 = blockIdx.x * 32;
    int c0 = blockIdx.y * 32;
    const float* xb = x + (size_t)b * C_IN * HW;
    #pragma unroll
    for (int i = threadIdx.y; i < 32; i += 8)
        tile[i][threadIdx.x] = xb[(size_t)(c0 + i) * HW + hw0 + threadIdx.x];
    __syncthreads();
    float* xt = g_xt + (size_t)b * HW * C_IN;
    #pragma unroll
    for (int i = threadIdx.y; i < 32; i += 8)
        xt[(size_t)(hw0 + i) * C_IN + c0 + threadIdx.x] = tile[threadIdx.x][i];
}

// ---------------------------------------------------------------------------
// Weight transposes
// ---------------------------------------------------------------------------
__global__ void transpose_w_kernel(const float* __restrict__ wo,
                                   const float* __restrict__ wc) {
    int i = blockIdx.x * 256 + threadIdx.x;
    if (i < K2 * C_IN * C_OUT) {
        int o = i & 127;
        int c = (i >> 7) & 127;
        int k = i >> 14;
        g_wT[i] = wc[(o * 128 + c) * 9 + k];
    }
    if (i < K2 * C_IN * NOFF) {
        int oc = i % 18;
        int rem = i / 18;
        int c = rem & 127;
        int k = rem >> 7;
        g_woT[i] = wo[(oc * 128 + c) * 9 + k];
    }
}

// ---------------------------------------------------------------------------
// Offset conv: 3x3 conv, 18 oc, implicit GEMM. Block = 2 rows (128 px).
// ---------------------------------------------------------------------------
__global__ __launch_bounds__(256) void offset_conv_kernel() {
    __shared__ float a_s[128][33];
    __shared__ float w_s[32][20];

    int b = blockIdx.x >> 5;
    int h0 = (blockIdx.x & 31) * 2;
    int tid = threadIdx.x;
    int pp = tid & 63;
    int g = tid >> 6;

    float acc[2][5] = {};

    for (int tap = 0; tap < 9; tap++) {
        int ky = tap / 3, kx = tap % 3;
        for (int c0 = 0; c0 < 128; c0 += 32) {
            #pragma unroll
            for (int i = 0; i < 16; i++) {
                int idx = tid + 256 * i;
                int c = idx & 31, p = idx >> 5;
                int y = h0 + (p >> 6) + ky - 1;
                int xx = (p & 63) + kx - 1;
                float v = 0.f;
                if ((unsigned)y < 64u && (unsigned)xx < 64u)
                    v = g_xt[(((b * 64 + y) * 64 + xx) << 7) + c0 + c];
                a_s[p][c] = v;
            }
            #pragma unroll
            for (int i = 0; i < 3; i++) {
                int idx = tid + 256 * i;
                if (idx < 640) {
                    int c = idx / 20, oc = idx % 20;
                    w_s[c][oc] = (oc < 18)
                        ? g_woT[(tap * 128 + c0 + c) * 18 + oc] : 0.f;
                }
            }
            __syncthreads();
            #pragma unroll
            for (int c = 0; c < 32; c++) {
                float a0 = a_s[pp][c];
                float a1 = a_s[pp + 64][c];
                #pragma unroll
                for (int j = 0; j < 5; j++) {
                    float wv = w_s[c][g + 4 * j];
                    acc[0][j] += a0 * wv;
                    acc[1][j] += a1 * wv;
                }
            }
            __syncthreads();
        }
    }
    #pragma unroll
    for (int r = 0; r < 2; r++) {
        int p = pp + 64 * r;
        int h = h0 + (p >> 6), w = p & 63;
        #pragma unroll
        for (int j = 0; j < 5; j++) {
            int oc = g + 4 * j;
            if (oc < 18)
                g_off[((b * 18 + oc) * 64 + h) * 64 + w] = acc[r][j];
        }
    }
}

// ---------------------------------------------------------------------------
// Deformable conv: block = 128 pixels x 128 outputs, 256 threads.
// Micro-tile 8 px x 8 out per thread -> 1.0 B LDS per FFMA.
// Grid MUST be Bn * (HW/128) = 256 blocks (b = blockIdx.x >> 5).
// ---------------------------------------------------------------------------
__global__ __launch_bounds__(256, 2) void deform_kernel(float* __restrict__ out) {
    __shared__ float w_s[32][128];    // [cin_chunk][o]
    __shared__ float v_s[128][36];    // [pixel][cin_chunk] (padded)
    __shared__ float cw[4][128];      // per-corner bilinear weights (0 if OOB)
    __shared__ int   coff[4][128];    // per-corner clamped (y*64+x)*128 offsets

    int b = blockIdx.x >> 5;               // 32 blocks per image
    int pix0 = (blockIdx.x & 31) * 128;
    int tid = threadIdx.x;
    int lane = tid & 31;
    int warp = tid >> 5;
    int tx = tid & 15;                     // out group: o = tx*8..tx*8+7
    int ty = tid >> 4;                     // px group:  p = ty*8..ty*8+7

    const float* xb = g_xt + (size_t)b * HW * C_IN;
    float acc[8][8] = {};                  // [out][px]

    for (int k = 0; k < 9; k++) {
        // Per-(pixel, tap) sampling setup (first 4 warps, 1 thread/pixel)
        if (tid < 128) {
            int p = tid;
            int gp = pix0 + p;
            int h = gp >> 6, w = gp & 63;
            float dy = g_off[((b * 18 + 2 * k) * 64 + h) * 64 + w];
            float dx = g_off[((b * 18 + 2 * k + 1) * 64 + h) * 64 + w];
            float py = (float)(h - 1 + k / 3) + dy;
            float px = (float)(w - 1 + k % 3) + dx;
            float y0f = floorf(py), x0f = floorf(px);
            float fy = py - y0f, fx = px - x0f;
            #pragma unroll
            for (int j = 0; j < 4; j++) {
                float yf = y0f + (float)(j >> 1);
                float xf = x0f + (float)(j & 1);
                bool ok = (yf >= 0.f && yf < 64.f && xf >= 0.f && xf < 64.f);
                float wy = (j >> 1) ? fy : 1.f - fy;
                float wx = (j & 1) ? fx : 1.f - fx;
                cw[j][p] = ok ? wy * wx : 0.f;
                int yi = (int)fminf(fmaxf(yf, 0.f), 63.f);
                int xi = (int)fminf(fmaxf(xf, 0.f), 63.f);
                coff[j][p] = ((yi << 6) + xi) << 7;
            }
        }
        __syncthreads();

        for (int c0 = 0; c0 < 128; c0 += 32) {
            // Stage W: 32 cin x 128 o, coalesced (lane = o)
            #pragma unroll
            for (int i = 0; i < 16; i++) {
                int idx = tid + 256 * i;
                int c = idx >> 7, o = idx & 127;
                w_s[c][o] = g_wT[(k * 128 + c0 + c) * 128 + o];
            }
            // Gather: warp handles 16 pixels, lane = cin within chunk.
            // 128B-coalesced corner reads, warp-uniform zero-weight skip.
            #pragma unroll
            for (int i = 0; i < 16; i++) {
                int p = warp * 16 + i;
                float a = 0.f;
                #pragma unroll
                for (int j = 0; j < 4; j++) {
                    float wgt = cw[j][p];
                    if (wgt != 0.f)
                        a += wgt * xb[coff[j][p] + c0 + lane];
                }
                v_s[p][lane] = a;
            }
            __syncthreads();

            // MMA: 8 px x 8 out per thread. Per c4-step (4 cin):
            // 8 w LDS.128 (held in regs) + 8 transient v LDS.128, 256 FFMA.
            #pragma unroll
            for (int c4 = 0; c4 < 8; c4++) {
                float4 w0[4], w1[4];
                #pragma unroll
                for (int cc = 0; cc < 4; cc++) {
                    w0[cc] = *(const float4*)&w_s[c4 * 4 + cc][tx * 8];
                    w1[cc] = *(const float4*)&w_s[c4 * 4 + cc][tx * 8 + 4];
                }
                #pragma unroll
                for (int pp = 0; pp < 8; pp++) {
                    float4 va = *(const float4*)&v_s[ty * 8 + pp][c4 * 4];
                    float vv[4] = {va.x, va.y, va.z, va.w};
                    #pragma unroll
                    for (int cc = 0; cc < 4; cc++) {
                        acc[0][pp] += vv[cc] * w0[cc].x;
                        acc[1][pp] += vv[cc] * w0[cc].y;
                        acc[2][pp] += vv[cc] * w0[cc].z;
                        acc[3][pp] += vv[cc] * w0[cc].w;
                        acc[4][pp] += vv[cc] * w1[cc].x;
                        acc[5][pp] += vv[cc] * w1[cc].y;
                        acc[6][pp] += vv[cc] * w1[cc].z;
                        acc[7][pp] += vv[cc] * w1[cc].w;
                    }
                }
            }
            __syncthreads();
        }
    }

    // Store: 8 consecutive px per thread per out channel -> 2 STG.128 each
    float* ob = out + ((size_t)b * 128) * HW + pix0 + ty * 8;
    #pragma unroll
    for (int oo = 0; oo < 8; oo++) {
        int o = tx * 8 + oo;
        *(float4*)(ob + (size_t)o * HW) =
            make_float4(acc[oo][0], acc[oo][1], acc[oo][2], acc[oo][3]);
        *(float4*)(ob + (size_t)o * HW + 4) =
            make_float4(acc[oo][4], acc[oo][5], acc[oo][6], acc[oo][7]);
    }
}

// ---------------------------------------------------------------------------
extern "C" void kernel_launch(void* const* d_in, const int* in_sizes, int n_in,
                              void* d_out, int out_size) {
    const float* x  = (const float*)d_in[0];
    const float* wo = (const float*)d_in[1];   // w_offset
    const float* wc = (const float*)d_in[2];   // w_conv
    float* out = (float*)d_out;

    dim3 tpb(32, 8);
    transpose_x_kernel<<<dim3(HW / 32, C_IN / 32, Bn), tpb>>>(x);
    transpose_w_kernel<<<(K2 * C_IN * C_OUT + 255) / 256, 256>>>(wo, wc);
    offset_conv_kernel<<<Bn * (HH / 2), 256>>>();
    deform_kernel<<<Bn * (HW / 128), 256>>>(out);   // 256 blocks: b = blk>>5
}

// round 7
// speedup vs baseline: 2.0583x; 2.0085x over previous
#include <cuda_runtime.h>
#include <cuda_bf16.h>
#include <cstdint>

#define Bn 8
#define C_IN 128
#define C_OUT 128
#define K2 9
#define HH 64
#define WW 64
#define HW 4096
#define NOFF 18

// Scratch (no cudaMalloc allowed)
__device__ float g_xt[Bn * HW * C_IN];            // x NHWC: [b][y][x][c]
__device__ float g_woT[K2 * C_IN * NOFF];         // w_offset: [k][cin][oc]
__device__ float g_off[Bn * NOFF * HW];           // offsets: [b][ch][y][x]
__device__ __nv_bfloat16 g_wh[K2 * C_OUT * C_IN]; // w_conv hi: [k][o][cin]
__device__ __nv_bfloat16 g_wl[K2 * C_OUT * C_IN]; // w_conv lo: [k][o][cin]

// ---------------------------------------------------------------------------
// Helpers (portable PTX only: ldmatrix + mma.sync, sm_80+)
// ---------------------------------------------------------------------------
__device__ __forceinline__ uint32_t smem_u32(const void* p) {
    uint32_t a;
    asm("{ .reg .u64 t; cvta.to.shared.u64 t, %1; cvt.u32.u64 %0, t; }"
        : "=r"(a) : "l"(p));
    return a;
}
__device__ __forceinline__ void ldsm_x4(uint32_t* r, uint32_t addr) {
    asm volatile("ldmatrix.sync.aligned.m8n8.x4.shared.b16 {%0,%1,%2,%3}, [%4];"
                 : "=r"(r[0]), "=r"(r[1]), "=r"(r[2]), "=r"(r[3]) : "r"(addr));
}
__device__ __forceinline__ void mma_bf16(float* c, const uint32_t* a,
                                         const uint32_t* b) {
    asm volatile(
        "mma.sync.aligned.m16n8k16.row.col.f32.bf16.bf16.f32 "
        "{%0,%1,%2,%3}, {%4,%5,%6,%7}, {%8,%9}, {%0,%1,%2,%3};"
        : "+f"(c[0]), "+f"(c[1]), "+f"(c[2]), "+f"(c[3])
        : "r"(a[0]), "r"(a[1]), "r"(a[2]), "r"(a[3]), "r"(b[0]), "r"(b[1]));
}

// ---------------------------------------------------------------------------
// NCHW -> NHWC transpose of x
// ---------------------------------------------------------------------------
__global__ void transpose_x_kernel(const float* __restrict__ x) {
    __shared__ float tile[32][33];
    int b = blockIdx.z;
    int hw0 = blockIdx.x * 32;
    int c0 = blockIdx.y * 32;
    const float* xb = x + (size_t)b * C_IN * HW;
    #pragma unroll
    for (int i = threadIdx.y; i < 32; i += 8)
        tile[i][threadIdx.x] = xb[(size_t)(c0 + i) * HW + hw0 + threadIdx.x];
    __syncthreads();
    float* xt = g_xt + (size_t)b * HW * C_IN;
    #pragma unroll
    for (int i = threadIdx.y; i < 32; i += 8)
        xt[(size_t)(hw0 + i) * C_IN + c0 + threadIdx.x] = tile[threadIdx.x][i];
}

// ---------------------------------------------------------------------------
// Weight prep: w_offset -> g_woT;  w_conv -> bf16 hi/lo split [k][o][cin]
// ---------------------------------------------------------------------------
__global__ void prep_w_kernel(const float* __restrict__ wo,
                              const float* __restrict__ wc) {
    int i = blockIdx.x * 256 + threadIdx.x;
    if (i < K2 * C_OUT * C_IN) {
        int c = i & 127;
        int o = (i >> 7) & 127;
        int k = i >> 14;
        float v = wc[(o * 128 + c) * 9 + k];
        __nv_bfloat16 hi = __float2bfloat16_rn(v);
        __nv_bfloat16 lo = __float2bfloat16_rn(v - __bfloat162float(hi));
        g_wh[i] = hi;
        g_wl[i] = lo;
    }
    if (i < K2 * C_IN * NOFF) {
        int oc = i % 18;
        int rem = i / 18;
        int c = rem & 127;
        int k = rem >> 7;
        g_woT[i] = wo[(oc * 128 + c) * 9 + k];
    }
}

// ---------------------------------------------------------------------------
// Offset conv: 3x3 conv, 18 oc, implicit GEMM. Block = 2 rows (128 px).
// ---------------------------------------------------------------------------
__global__ __launch_bounds__(256) void offset_conv_kernel() {
    __shared__ float a_s[128][33];
    __shared__ float w_s[32][20];

    int b = blockIdx.x >> 5;
    int h0 = (blockIdx.x & 31) * 2;
    int tid = threadIdx.x;
    int pp = tid & 63;
    int g = tid >> 6;

    float acc[2][5] = {};

    for (int tap = 0; tap < 9; tap++) {
        int ky = tap / 3, kx = tap % 3;
        for (int c0 = 0; c0 < 128; c0 += 32) {
            #pragma unroll
            for (int i = 0; i < 16; i++) {
                int idx = tid + 256 * i;
                int c = idx & 31, p = idx >> 5;
                int y = h0 + (p >> 6) + ky - 1;
                int xx = (p & 63) + kx - 1;
                float v = 0.f;
                if ((unsigned)y < 64u && (unsigned)xx < 64u)
                    v = g_xt[(((b * 64 + y) * 64 + xx) << 7) + c0 + c];
                a_s[p][c] = v;
            }
            #pragma unroll
            for (int i = 0; i < 3; i++) {
                int idx = tid + 256 * i;
                if (idx < 640) {
                    int c = idx / 20, oc = idx % 20;
                    w_s[c][oc] = (oc < 18)
                        ? g_woT[(tap * 128 + c0 + c) * 18 + oc] : 0.f;
                }
            }
            __syncthreads();
            #pragma unroll
            for (int c = 0; c < 32; c++) {
                float a0 = a_s[pp][c];
                float a1 = a_s[pp + 64][c];
                #pragma unroll
                for (int j = 0; j < 5; j++) {
                    float wv = w_s[c][g + 4 * j];
                    acc[0][j] += a0 * wv;
                    acc[1][j] += a1 * wv;
                }
            }
            __syncthreads();
        }
    }
    #pragma unroll
    for (int r = 0; r < 2; r++) {
        int p = pp + 64 * r;
        int h = h0 + (p >> 6), w = p & 63;
        #pragma unroll
        for (int j = 0; j < 5; j++) {
            int oc = g + 4 * j;
            if (oc < 18)
                g_off[((b * 18 + oc) * 64 + h) * 64 + w] = acc[r][j];
        }
    }
}

// ---------------------------------------------------------------------------
// Tensor-core deformable conv via ldmatrix + mma.sync (portable PTX).
// Block tile: M=128 px, N=128 out. 8 warps: each 32 px x 64 out.
// 3-term bf16 split: Ah*Wh + Al*Wh + Ah*Wl, fp32 accumulate.
// SMEM (dynamic, 102400 B):
//   [0]      A_hi 128x128 bf16 (32KB, XOR-swizzled rows of 16x16B chunks)
//   [32768]  A_lo (32KB)
//   [65536]  W_hi 128o x 64cin bf16 (16KB, half-K staging)
//   [81920]  W_lo (16KB)
//   [98304]  cw 4x128 f32   [100352] coff 4x128 i32
// ---------------------------------------------------------------------------
#define SM_AHI 0u
#define SM_ALO 32768u
#define SM_WHI 65536u
#define SM_WLO 81920u
#define SM_CW  98304u
#define SM_CO  100352u
#define SMEM_BYTES 102400

__global__ __launch_bounds__(256, 2) void deform_mma(float* __restrict__ out) {
    extern __shared__ char smem[];
    const uint32_t sb = smem_u32(smem);
    const int tid = threadIdx.x;
    const int lane = tid & 31;
    const int wid = tid >> 5;
    const int b = blockIdx.x >> 5;
    const int pix0 = (blockIdx.x & 31) * 128;

    const int wy = wid & 3;          // px group: 32 px
    const int wx = wid >> 2;         // out group: 64 o

    float* cw = (float*)(smem + SM_CW);
    int* coff = (int*)(smem + SM_CO);
    const float* xb = g_xt + (size_t)b * HW * C_IN;
    const uint32_t* whp = (const uint32_t*)g_wh;
    const uint32_t* wlp = (const uint32_t*)g_wl;

    float acc[2][8][4] = {};         // [m-tile][n-tile(8 wide)][frag]

    for (int k = 0; k < 9; k++) {
        // --- per-(pixel, tap) bilinear setup (1 thread per pixel) ---
        if (tid < 128) {
            int p = tid;
            int gp = pix0 + p;
            int h = gp >> 6, w = gp & 63;
            float dy = g_off[((b * 18 + 2 * k) * 64 + h) * 64 + w];
            float dx = g_off[((b * 18 + 2 * k + 1) * 64 + h) * 64 + w];
            float py = (float)(h - 1 + k / 3) + dy;
            float px = (float)(w - 1 + k % 3) + dx;
            float y0f = floorf(py), x0f = floorf(px);
            float fy = py - y0f, fx = px - x0f;
            #pragma unroll
            for (int j = 0; j < 4; j++) {
                float yf = y0f + (float)(j >> 1);
                float xf = x0f + (float)(j & 1);
                bool ok = (yf >= 0.f && yf < 64.f && xf >= 0.f && xf < 64.f);
                float wy_ = (j >> 1) ? fy : 1.f - fy;
                float wx_ = (j & 1) ? fx : 1.f - fx;
                cw[j * 128 + p] = ok ? wy_ * wx_ : 0.f;
                int yi = (int)fminf(fmaxf(yf, 0.f), 63.f);
                int xi = (int)fminf(fmaxf(xf, 0.f), 63.f);
                coff[j * 128 + p] = ((yi << 6) + xi) << 7;
            }
        }
        __syncthreads();

        // --- gather: warp = 16 px, lane = cin pair; bf16 hi/lo into A tiles ---
        for (int i = 0; i < 16; i++) {
            int p = wid * 16 + i;
            float wgt0 = cw[0 * 128 + p], wgt1 = cw[1 * 128 + p];
            float wgt2 = cw[2 * 128 + p], wgt3 = cw[3 * 128 + p];
            int cof0 = coff[0 * 128 + p], cof1 = coff[1 * 128 + p];
            int cof2 = coff[2 * 128 + p], cof3 = coff[3 * 128 + p];
            #pragma unroll
            for (int c0 = 0; c0 < 128; c0 += 64) {
                float vx = 0.f, vy = 0.f;
                const float* base = xb + c0 + 2 * lane;
                if (wgt0 != 0.f) { float2 t = *(const float2*)(base + cof0); vx += wgt0 * t.x; vy += wgt0 * t.y; }
                if (wgt1 != 0.f) { float2 t = *(const float2*)(base + cof1); vx += wgt1 * t.x; vy += wgt1 * t.y; }
                if (wgt2 != 0.f) { float2 t = *(const float2*)(base + cof2); vx += wgt2 * t.x; vy += wgt2 * t.y; }
                if (wgt3 != 0.f) { float2 t = *(const float2*)(base + cof3); vx += wgt3 * t.x; vy += wgt3 * t.y; }
                __nv_bfloat16 hx = __float2bfloat16_rn(vx);
                __nv_bfloat16 hy = __float2bfloat16_rn(vy);
                __nv_bfloat16 lx = __float2bfloat16_rn(vx - __bfloat162float(hx));
                __nv_bfloat16 ly = __float2bfloat16_rn(vy - __bfloat162float(hy));
                uint32_t hp = (uint32_t)__bfloat16_as_ushort(hx)
                            | ((uint32_t)__bfloat16_as_ushort(hy) << 16);
                uint32_t lp = (uint32_t)__bfloat16_as_ushort(lx)
                            | ((uint32_t)__bfloat16_as_ushort(ly) << 16);
                // A row = 256B = 16 chunks of 16B; swizzle chunk ^= (row & 7)
                uint32_t chunk = (uint32_t)(c0 >> 3) + (uint32_t)(lane >> 2);
                uint32_t sw = (uint32_t)p * 256u
                            + ((chunk ^ ((uint32_t)p & 7u)) << 4)
                            + ((uint32_t)(lane & 3) << 2);
                *(uint32_t*)(smem + SM_AHI + sw) = hp;
                *(uint32_t*)(smem + SM_ALO + sw) = lp;
            }
        }

        for (int half = 0; half < 2; half++) {
            // --- stage W hi/lo half-K tiles: [128 o][64 cin] ---
            #pragma unroll
            for (int t = 0; t < 16; t++) {
                int idx = tid + 256 * t;
                int r = idx >> 5, j = idx & 31;        // o row, cin pair
                uint32_t chunk = (uint32_t)(j >> 2);   // 0..7 (128B rows)
                uint32_t sw = (uint32_t)r * 128u
                            + ((chunk ^ ((uint32_t)r & 7u)) << 4)
                            + ((uint32_t)(j & 3) << 2);
                int gi = (k * 128 + r) * 64 + half * 32 + j;
                *(uint32_t*)(smem + SM_WHI + sw) = whp[gi];
                *(uint32_t*)(smem + SM_WLO + sw) = wlp[gi];
            }
            __syncthreads();   // A (first half) + W visible to all warps

            // --- MMA: 4 k16-chunks per half ---
            #pragma unroll
            for (int kc = 0; kc < 4; kc++) {
                int kbase = half * 64 + kc * 16;
                uint32_t ah[2][4], al[2][4];
                #pragma unroll
                for (int mt = 0; mt < 2; mt++) {
                    int mat = lane >> 3;
                    int arow = wy * 32 + mt * 16 + (lane & 7) + ((mat & 1) << 3);
                    int kcol = kbase + ((mat >> 1) << 3);
                    uint32_t chunk = (uint32_t)(kcol >> 3);
                    uint32_t aoff = (uint32_t)arow * 256u
                                  + ((chunk ^ ((uint32_t)arow & 7u)) << 4);
                    ldsm_x4(ah[mt], sb + SM_AHI + aoff);
                    ldsm_x4(al[mt], sb + SM_ALO + aoff);
                }
                #pragma unroll
                for (int ng = 0; ng < 4; ng++) {
                    // W frags for two n8 tiles: mats {n0-7,k0},{n0-7,k8},
                    //                                {n8-15,k0},{n8-15,k8}
                    int wrow = wx * 64 + ng * 16 + (lane & 7) + ((lane >> 4) << 3);
                    int kcol = kc * 16 + (((lane >> 3) & 1) << 3);
                    uint32_t chunk = (uint32_t)(kcol >> 3);
                    uint32_t woff = (uint32_t)wrow * 128u
                                  + ((chunk ^ ((uint32_t)wrow & 7u)) << 4);
                    uint32_t wh[4], wl[4];
                    ldsm_x4(wh, sb + SM_WHI + woff);
                    ldsm_x4(wl, sb + SM_WLO + woff);
                    #pragma unroll
                    for (int mt = 0; mt < 2; mt++) {
                        mma_bf16(acc[mt][ng * 2 + 0], ah[mt], wh + 0);
                        mma_bf16(acc[mt][ng * 2 + 1], ah[mt], wh + 2);
                        mma_bf16(acc[mt][ng * 2 + 0], al[mt], wh + 0);
                        mma_bf16(acc[mt][ng * 2 + 1], al[mt], wh + 2);
                        mma_bf16(acc[mt][ng * 2 + 0], ah[mt], wl + 0);
                        mma_bf16(acc[mt][ng * 2 + 1], ah[mt], wl + 2);
                    }
                }
            }
            __syncthreads();   // all warps done reading W (and A on last half)
        }
    }

    // --- epilogue: c-frag -> out[b][o][px] ---
    // frag: rows (px) = mbase + lane/4 (+8), cols (o) = nbase + (lane%4)*2 (+1)
    float* ob = out + (size_t)b * 128 * HW;
    #pragma unroll
    for (int mt = 0; mt < 2; mt++) {
        int px0 = pix0 + wy * 32 + mt * 16 + (lane >> 2);
        #pragma unroll
        for (int nt = 0; nt < 8; nt++) {
            int o = wx * 64 + nt * 8 + (lane & 3) * 2;
            ob[(size_t)o * HW + px0]            = acc[mt][nt][0];
            ob[(size_t)(o + 1) * HW + px0]      = acc[mt][nt][1];
            ob[(size_t)o * HW + px0 + 8]        = acc[mt][nt][2];
            ob[(size_t)(o + 1) * HW + px0 + 8]  = acc[mt][nt][3];
        }
    }
}

// ---------------------------------------------------------------------------
extern "C" void kernel_launch(void* const* d_in, const int* in_sizes, int n_in,
                              void* d_out, int out_size) {
    const float* x  = (const float*)d_in[0];
    const float* wo = (const float*)d_in[1];   // w_offset
    const float* wc = (const float*)d_in[2];   // w_conv
    float* out = (float*)d_out;

    static bool attr_set = false;
    if (!attr_set) {
        cudaFuncSetAttribute(deform_mma,
                             cudaFuncAttributeMaxDynamicSharedMemorySize,
                             SMEM_BYTES);
        attr_set = true;
    }

    dim3 tpb(32, 8);
    transpose_x_kernel<<<dim3(HW / 32, C_IN / 32, Bn), tpb>>>(x);
    prep_w_kernel<<<(K2 * C_OUT * C_IN + 255) / 256, 256>>>(wo, wc);
    offset_conv_kernel<<<Bn * (HH / 2), 256>>>();
    deform_mma<<<Bn * (HW / 128), 256, SMEM_BYTES>>>(out);
}

// round 8
// speedup vs baseline: 2.5973x; 1.2619x over previous
#include <cuda_runtime.h>
#include <cuda_bf16.h>
#include <cstdint>

#define Bn 8
#define C_IN 128
#define C_OUT 128
#define K2 9
#define HH 64
#define WW 64
#define HW 4096
#define NOFF 18

// Scratch (no cudaMalloc allowed)
__device__ float g_xt[Bn * HW * C_IN];            // x NHWC: [b][y][x][c]
__device__ float g_off[Bn * NOFF * HW];           // offsets: [b][ch][y][x]
__device__ __nv_bfloat16 g_wh[K2 * C_OUT * C_IN]; // w_conv hi: [k][o][cin]
__device__ __nv_bfloat16 g_wl[K2 * C_OUT * C_IN]; // w_conv lo: [k][o][cin]
__device__ __nv_bfloat16 g_woh[K2 * 32 * C_IN];   // w_offset hi: [k][oc(pad32)][cin]
__device__ __nv_bfloat16 g_wol[K2 * 32 * C_IN];   // w_offset lo

// ---------------------------------------------------------------------------
// Helpers (portable PTX only: ldmatrix + mma.sync, sm_80+)
// ---------------------------------------------------------------------------
__device__ __forceinline__ uint32_t smem_u32(const void* p) {
    uint32_t a;
    asm("{ .reg .u64 t; cvta.to.shared.u64 t, %1; cvt.u32.u64 %0, t; }"
        : "=r"(a) : "l"(p));
    return a;
}
__device__ __forceinline__ void ldsm_x4(uint32_t* r, uint32_t addr) {
    asm volatile("ldmatrix.sync.aligned.m8n8.x4.shared.b16 {%0,%1,%2,%3}, [%4];"
                 : "=r"(r[0]), "=r"(r[1]), "=r"(r[2]), "=r"(r[3]) : "r"(addr));
}
__device__ __forceinline__ void mma_bf16(float* c, const uint32_t* a,
                                         const uint32_t* b) {
    asm volatile(
        "mma.sync.aligned.m16n8k16.row.col.f32.bf16.bf16.f32 "
        "{%0,%1,%2,%3}, {%4,%5,%6,%7}, {%8,%9}, {%0,%1,%2,%3};"
        : "+f"(c[0]), "+f"(c[1]), "+f"(c[2]), "+f"(c[3])
        : "r"(a[0]), "r"(a[1]), "r"(a[2]), "r"(a[3]), "r"(b[0]), "r"(b[1]));
}
__device__ __forceinline__ void split_pack(float vx, float vy,
                                           uint32_t& hp, uint32_t& lp) {
    __nv_bfloat16 hx = __float2bfloat16_rn(vx);
    __nv_bfloat16 hy = __float2bfloat16_rn(vy);
    __nv_bfloat16 lx = __float2bfloat16_rn(vx - __bfloat162float(hx));
    __nv_bfloat16 ly = __float2bfloat16_rn(vy - __bfloat162float(hy));
    hp = (uint32_t)__bfloat16_as_ushort(hx)
       | ((uint32_t)__bfloat16_as_ushort(hy) << 16);
    lp = (uint32_t)__bfloat16_as_ushort(lx)
       | ((uint32_t)__bfloat16_as_ushort(ly) << 16);
}

// ---------------------------------------------------------------------------
// NCHW -> NHWC transpose of x
// ---------------------------------------------------------------------------
__global__ void transpose_x_kernel(const float* __restrict__ x) {
    __shared__ float tile[32][33];
    int b = blockIdx.z;
    int hw0 = blockIdx.x * 32;
    int c0 = blockIdx.y * 32;
    const float* xb = x + (size_t)b * C_IN * HW;
    #pragma unroll
    for (int i = threadIdx.y; i < 32; i += 8)
        tile[i][threadIdx.x] = xb[(size_t)(c0 + i) * HW + hw0 + threadIdx.x];
    __syncthreads();
    float* xt = g_xt + (size_t)b * HW * C_IN;
    #pragma unroll
    for (int i = threadIdx.y; i < 32; i += 8)
        xt[(size_t)(hw0 + i) * C_IN + c0 + threadIdx.x] = tile[threadIdx.x][i];
}

// ---------------------------------------------------------------------------
// Weight prep: bf16 hi/lo splits. w_conv -> [k][o][cin]; w_offset -> [k][oc pad32][cin]
// ---------------------------------------------------------------------------
__global__ void prep_w_kernel(const float* __restrict__ wo,
                              const float* __restrict__ wc) {
    int i = blockIdx.x * 256 + threadIdx.x;
    if (i < K2 * C_OUT * C_IN) {
        int c = i & 127;
        int o = (i >> 7) & 127;
        int k = i >> 14;
        float v = wc[(o * 128 + c) * 9 + k];
        __nv_bfloat16 hi = __float2bfloat16_rn(v);
        __nv_bfloat16 lo = __float2bfloat16_rn(v - __bfloat162float(hi));
        g_wh[i] = hi;
        g_wl[i] = lo;
    }
    if (i < K2 * 32 * C_IN) {
        int c = i & 127;
        int oc = (i >> 7) & 31;
        int k = i >> 12;
        float v = (oc < 18) ? wo[(oc * 128 + c) * 9 + k] : 0.f;
        __nv_bfloat16 hi = __float2bfloat16_rn(v);
        __nv_bfloat16 lo = __float2bfloat16_rn(v - __bfloat162float(hi));
        g_woh[i] = hi;
        g_wol[i] = lo;
    }
}

// ---------------------------------------------------------------------------
// Offset conv via tensor cores: M=128 px, N=32 (18 used), K=1152.
// Per tap: im2col A staging (regular shifts), 3-term bf16 split MMA.
// SMEM (81920 B): A_hi[0,32K) A_lo[32K,64K) W_hi[64K,72K) W_lo[72K,80K)
// A/W rows = 256B (128 cin), XOR swizzle chunk ^= (row & 7).
// ---------------------------------------------------------------------------
#define OSM_AHI 0u
#define OSM_ALO 32768u
#define OSM_WHI 65536u
#define OSM_WLO 73728u
#define OSMEM_BYTES 81920

__global__ __launch_bounds__(256, 2) void offset_mma() {
    extern __shared__ char smem[];
    const uint32_t sb = smem_u32(smem);
    const int tid = threadIdx.x;
    const int lane = tid & 31;
    const int wid = tid >> 5;
    const int b = blockIdx.x >> 5;
    const int pix0 = (blockIdx.x & 31) * 128;

    const float* xb = g_xt + (size_t)b * HW * C_IN;
    const uint32_t* whp = (const uint32_t*)g_woh;
    const uint32_t* wlp = (const uint32_t*)g_wol;

    float acc[4][4] = {};   // 4 n8-tiles x frag

    for (int k = 0; k < 9; k++) {
        int ky = k / 3 - 1, kx = k % 3 - 1;
        // --- stage A: im2col tap slice [128 px][128 cin] bf16 hi/lo ---
        #pragma unroll
        for (int t = 0; t < 32; t++) {
            int idx = tid + 256 * t;
            int p = idx >> 6, j = idx & 63;      // px, cin-pair
            int gp = pix0 + p;
            int y = (gp >> 6) + ky;
            int xx = (gp & 63) + kx;
            float2 v = make_float2(0.f, 0.f);
            if ((unsigned)y < 64u && (unsigned)xx < 64u)
                v = *(const float2*)&xb[(((y << 6) + xx) << 7) + 2 * j];
            uint32_t hp, lp;
            split_pack(v.x, v.y, hp, lp);
            uint32_t chunk = (uint32_t)(j >> 2);
            uint32_t sw = (uint32_t)p * 256u
                        + ((chunk ^ ((uint32_t)p & 7u)) << 4)
                        + ((uint32_t)(j & 3) << 2);
            *(uint32_t*)(smem + OSM_AHI + sw) = hp;
            *(uint32_t*)(smem + OSM_ALO + sw) = lp;
        }
        // --- stage W: [32 oc][128 cin] hi/lo ---
        #pragma unroll
        for (int t = 0; t < 8; t++) {
            int idx = tid + 256 * t;
            int r = idx >> 6, j = idx & 63;
            uint32_t chunk = (uint32_t)(j >> 2);
            uint32_t sw = (uint32_t)r * 256u
                        + ((chunk ^ ((uint32_t)r & 7u)) << 4)
                        + ((uint32_t)(j & 3) << 2);
            int gi = (k * 32 + r) * 64 + j;
            *(uint32_t*)(smem + OSM_WHI + sw) = whp[gi];
            *(uint32_t*)(smem + OSM_WLO + sw) = wlp[gi];
        }
        __syncthreads();

        // --- MMA: warp = 16 px x 32 oc; 8 k16-chunks ---
        #pragma unroll
        for (int kc = 0; kc < 8; kc++) {
            uint32_t ah[4], al[4];
            int mat = lane >> 3;
            int arow = wid * 16 + (lane & 7) + ((mat & 1) << 3);
            int kcol = kc * 16 + ((mat >> 1) << 3);
            uint32_t chunk = (uint32_t)(kcol >> 3);
            uint32_t aoff = (uint32_t)arow * 256u
                          + ((chunk ^ ((uint32_t)arow & 7u)) << 4);
            ldsm_x4(ah, sb + OSM_AHI + aoff);
            ldsm_x4(al, sb + OSM_ALO + aoff);
            #pragma unroll
            for (int ng = 0; ng < 2; ng++) {
                int wrow = ng * 16 + (lane & 7) + ((lane >> 4) << 3);
                int kcol2 = kc * 16 + (((lane >> 3) & 1) << 3);
                uint32_t ch2 = (uint32_t)(kcol2 >> 3);
                uint32_t woff = (uint32_t)wrow * 256u
                              + ((ch2 ^ ((uint32_t)wrow & 7u)) << 4);
                uint32_t wh[4], wl[4];
                ldsm_x4(wh, sb + OSM_WHI + woff);
                ldsm_x4(wl, sb + OSM_WLO + woff);
                mma_bf16(acc[ng * 2 + 0], ah, wh + 0);
                mma_bf16(acc[ng * 2 + 1], ah, wh + 2);
                mma_bf16(acc[ng * 2 + 0], al, wh + 0);
                mma_bf16(acc[ng * 2 + 1], al, wh + 2);
                mma_bf16(acc[ng * 2 + 0], ah, wl + 0);
                mma_bf16(acc[ng * 2 + 1], ah, wl + 2);
            }
        }
        __syncthreads();
    }

    // --- epilogue: store g_off[b][ch][px] for ch < 18 ---
    int px0 = pix0 + wid * 16 + (lane >> 2);
    #pragma unroll
    for (int nt = 0; nt < 4; nt++) {
        int ch = nt * 8 + (lane & 3) * 2;
        if (ch < 18) {
            float* op = g_off + ((size_t)b * 18 + ch) * HW;
            op[px0]       = acc[nt][0];
            op[HW + px0]  = acc[nt][1];
            op[px0 + 8]      = acc[nt][2];
            op[HW + px0 + 8] = acc[nt][3];
        }
    }
}

// ---------------------------------------------------------------------------
// Tensor-core deformable conv via ldmatrix + mma.sync (portable PTX).
// Block tile: M=128 px, N=128 out. 8 warps: each 32 px x 64 out.
// 3-term bf16 split: Ah*Wh + Al*Wh + Ah*Wl, fp32 accumulate.
// SMEM (dynamic, 102400 B):
//   [0] A_hi 32KB  [32K] A_lo 32KB  [64K] W_hi 16KB  [80K] W_lo 16KB
//   [96K] cw 4x128 f32  [98K] coff 4x128 i32
// ---------------------------------------------------------------------------
#define SM_AHI 0u
#define SM_ALO 32768u
#define SM_WHI 65536u
#define SM_WLO 81920u
#define SM_CW  98304u
#define SM_CO  100352u
#define SMEM_BYTES 102400

__global__ __launch_bounds__(256, 2) void deform_mma(float* __restrict__ out) {
    extern __shared__ char smem[];
    const uint32_t sb = smem_u32(smem);
    const int tid = threadIdx.x;
    const int lane = tid & 31;
    const int wid = tid >> 5;
    const int b = blockIdx.x >> 5;
    const int pix0 = (blockIdx.x & 31) * 128;

    const int wy = wid & 3;          // px group: 32 px
    const int wx = wid >> 2;         // out group: 64 o

    float* cw = (float*)(smem + SM_CW);
    int* coff = (int*)(smem + SM_CO);
    const float* xb = g_xt + (size_t)b * HW * C_IN;
    const uint32_t* whp = (const uint32_t*)g_wh;
    const uint32_t* wlp = (const uint32_t*)g_wl;

    float acc[2][8][4] = {};         // [m-tile][n-tile(8 wide)][frag]

    for (int k = 0; k < 9; k++) {
        // --- per-(pixel, tap) bilinear setup (1 thread per pixel) ---
        if (tid < 128) {
            int p = tid;
            int gp = pix0 + p;
            int h = gp >> 6, w = gp & 63;
            float dy = g_off[((b * 18 + 2 * k) * 64 + h) * 64 + w];
            float dx = g_off[((b * 18 + 2 * k + 1) * 64 + h) * 64 + w];
            float py = (float)(h - 1 + k / 3) + dy;
            float px = (float)(w - 1 + k % 3) + dx;
            float y0f = floorf(py), x0f = floorf(px);
            float fy = py - y0f, fx = px - x0f;
            #pragma unroll
            for (int j = 0; j < 4; j++) {
                float yf = y0f + (float)(j >> 1);
                float xf = x0f + (float)(j & 1);
                bool ok = (yf >= 0.f && yf < 64.f && xf >= 0.f && xf < 64.f);
                float wy_ = (j >> 1) ? fy : 1.f - fy;
                float wx_ = (j & 1) ? fx : 1.f - fx;
                cw[j * 128 + p] = ok ? wy_ * wx_ : 0.f;
                int yi = (int)fminf(fmaxf(yf, 0.f), 63.f);
                int xi = (int)fminf(fmaxf(xf, 0.f), 63.f);
                coff[j * 128 + p] = ((yi << 6) + xi) << 7;
            }
        }
        __syncthreads();

        // --- gather: warp = 16 px, lane = cin pair; bf16 hi/lo into A tiles ---
        for (int i = 0; i < 16; i++) {
            int p = wid * 16 + i;
            float wgt0 = cw[0 * 128 + p], wgt1 = cw[1 * 128 + p];
            float wgt2 = cw[2 * 128 + p], wgt3 = cw[3 * 128 + p];
            int cof0 = coff[0 * 128 + p], cof1 = coff[1 * 128 + p];
            int cof2 = coff[2 * 128 + p], cof3 = coff[3 * 128 + p];
            #pragma unroll
            for (int c0 = 0; c0 < 128; c0 += 64) {
                float vx = 0.f, vy = 0.f;
                const float* base = xb + c0 + 2 * lane;
                if (wgt0 != 0.f) { float2 t = *(const float2*)(base + cof0); vx += wgt0 * t.x; vy += wgt0 * t.y; }
                if (wgt1 != 0.f) { float2 t = *(const float2*)(base + cof1); vx += wgt1 * t.x; vy += wgt1 * t.y; }
                if (wgt2 != 0.f) { float2 t = *(const float2*)(base + cof2); vx += wgt2 * t.x; vy += wgt2 * t.y; }
                if (wgt3 != 0.f) { float2 t = *(const float2*)(base + cof3); vx += wgt3 * t.x; vy += wgt3 * t.y; }
                uint32_t hp, lp;
                split_pack(vx, vy, hp, lp);
                uint32_t chunk = (uint32_t)(c0 >> 3) + (uint32_t)(lane >> 2);
                uint32_t sw = (uint32_t)p * 256u
                            + ((chunk ^ ((uint32_t)p & 7u)) << 4)
                            + ((uint32_t)(lane & 3) << 2);
                *(uint32_t*)(smem + SM_AHI + sw) = hp;
                *(uint32_t*)(smem + SM_ALO + sw) = lp;
            }
        }

        for (int half = 0; half < 2; half++) {
            // --- stage W hi/lo half-K tiles: [128 o][64 cin] ---
            #pragma unroll
            for (int t = 0; t < 16; t++) {
                int idx = tid + 256 * t;
                int r = idx >> 5, j = idx & 31;        // o row, cin pair
                uint32_t chunk = (uint32_t)(j >> 2);   // 0..7 (128B rows)
                uint32_t sw = (uint32_t)r * 128u
                            + ((chunk ^ ((uint32_t)r & 7u)) << 4)
                            + ((uint32_t)(j & 3) << 2);
                int gi = (k * 128 + r) * 64 + half * 32 + j;
                *(uint32_t*)(smem + SM_WHI + sw) = whp[gi];
                *(uint32_t*)(smem + SM_WLO + sw) = wlp[gi];
            }
            __syncthreads();   // A (first half) + W visible to all warps

            // --- MMA: 4 k16-chunks per half ---
            #pragma unroll
            for (int kc = 0; kc < 4; kc++) {
                int kbase = half * 64 + kc * 16;
                uint32_t ah[2][4], al[2][4];
                #pragma unroll
                for (int mt = 0; mt < 2; mt++) {
                    int mat = lane >> 3;
                    int arow = wy * 32 + mt * 16 + (lane & 7) + ((mat & 1) << 3);
                    int kcol = kbase + ((mat >> 1) << 3);
                    uint32_t chunk = (uint32_t)(kcol >> 3);
                    uint32_t aoff = (uint32_t)arow * 256u
                                  + ((chunk ^ ((uint32_t)arow & 7u)) << 4);
                    ldsm_x4(ah[mt], sb + SM_AHI + aoff);
                    ldsm_x4(al[mt], sb + SM_ALO + aoff);
                }
                #pragma unroll
                for (int ng = 0; ng < 4; ng++) {
                    int wrow = wx * 64 + ng * 16 + (lane & 7) + ((lane >> 4) << 3);
                    int kcol = kc * 16 + (((lane >> 3) & 1) << 3);
                    uint32_t chunk = (uint32_t)(kcol >> 3);
                    uint32_t woff = (uint32_t)wrow * 128u
                                  + ((chunk ^ ((uint32_t)wrow & 7u)) << 4);
                    uint32_t wh[4], wl[4];
                    ldsm_x4(wh, sb + SM_WHI + woff);
                    ldsm_x4(wl, sb + SM_WLO + woff);
                    #pragma unroll
                    for (int mt = 0; mt < 2; mt++) {
                        mma_bf16(acc[mt][ng * 2 + 0], ah[mt], wh + 0);
                        mma_bf16(acc[mt][ng * 2 + 1], ah[mt], wh + 2);
                        mma_bf16(acc[mt][ng * 2 + 0], al[mt], wh + 0);
                        mma_bf16(acc[mt][ng * 2 + 1], al[mt], wh + 2);
                        mma_bf16(acc[mt][ng * 2 + 0], ah[mt], wl + 0);
                        mma_bf16(acc[mt][ng * 2 + 1], ah[mt], wl + 2);
                    }
                }
            }
            __syncthreads();   // all warps done reading W (and A on last half)
        }
    }

    // --- epilogue: c-frag -> out[b][o][px] ---
    float* ob = out + (size_t)b * 128 * HW;
    #pragma unroll
    for (int mt = 0; mt < 2; mt++) {
        int px0 = pix0 + wy * 32 + mt * 16 + (lane >> 2);
        #pragma unroll
        for (int nt = 0; nt < 8; nt++) {
            int o = wx * 64 + nt * 8 + (lane & 3) * 2;
            ob[(size_t)o * HW + px0]            = acc[mt][nt][0];
            ob[(size_t)(o + 1) * HW + px0]      = acc[mt][nt][1];
            ob[(size_t)o * HW + px0 + 8]        = acc[mt][nt][2];
            ob[(size_t)(o + 1) * HW + px0 + 8]  = acc[mt][nt][3];
        }
    }
}

// ---------------------------------------------------------------------------
extern "C" void kernel_launch(void* const* d_in, const int* in_sizes, int n_in,
                              void* d_out, int out_size) {
    const float* x  = (const float*)d_in[0];
    const float* wo = (const float*)d_in[1];   // w_offset
    const float* wc = (const float*)d_in[2];   // w_conv
    float* out = (float*)d_out;

    static bool attr_set = false;
    if (!attr_set) {
        cudaFuncSetAttribute(deform_mma,
                             cudaFuncAttributeMaxDynamicSharedMemorySize,
                             SMEM_BYTES);
        cudaFuncSetAttribute(offset_mma,
                             cudaFuncAttributeMaxDynamicSharedMemorySize,
                             OSMEM_BYTES);
        attr_set = true;
    }

    dim3 tpb(32, 8);
    transpose_x_kernel<<<dim3(HW / 32, C_IN / 32, Bn), tpb>>>(x);
    prep_w_kernel<<<(K2 * C_OUT * C_IN + 255) / 256, 256>>>(wo, wc);
    offset_mma<<<Bn * (HW / 128), 256, OSMEM_BYTES>>>();
    deform_mma<<<Bn * (HW / 128), 256, SMEM_BYTES>>>(out);
}

// round 9
// speedup vs baseline: 2.7816x; 1.0709x over previous
#include <cuda_runtime.h>
#include <cuda_bf16.h>
#include <cstdint>

#define Bn 8
#define C_IN 128
#define C_OUT 128
#define K2 9
#define HH 64
#define WW 64
#define HW 4096
#define NOFF 18

// Scratch (no cudaMalloc allowed)
__device__ float g_xt[Bn * HW * C_IN];            // x NHWC: [b][y][x][c]
__device__ float g_off[Bn * NOFF * HW];           // offsets: [b][ch][y][x]
__device__ __nv_bfloat16 g_woh[K2 * 32 * C_IN];   // w_offset hi: [k][oc(pad32)][cin]
__device__ __nv_bfloat16 g_wol[K2 * 32 * C_IN];   // w_offset lo
// w_conv in mma B-fragment order: [tap][o16-group(8)][k16(8)][lane(32)][mat(4)]
__device__ uint32_t g_wfh[K2 * 8 * 8 * 32 * 4];   // hi pairs
__device__ uint32_t g_wfl[K2 * 8 * 8 * 32 * 4];   // lo pairs

// ---------------------------------------------------------------------------
// Helpers (portable PTX only: ldmatrix + mma.sync, sm_80+)
// ---------------------------------------------------------------------------
__device__ __forceinline__ uint32_t smem_u32(const void* p) {
    uint32_t a;
    asm("{ .reg .u64 t; cvta.to.shared.u64 t, %1; cvt.u32.u64 %0, t; }"
        : "=r"(a) : "l"(p));
    return a;
}
__device__ __forceinline__ void ldsm_x4(uint32_t* r, uint32_t addr) {
    asm volatile("ldmatrix.sync.aligned.m8n8.x4.shared.b16 {%0,%1,%2,%3}, [%4];"
                 : "=r"(r[0]), "=r"(r[1]), "=r"(r[2]), "=r"(r[3]) : "r"(addr));
}
__device__ __forceinline__ void mma_bf16(float* c, const uint32_t* a,
                                         const uint32_t* b) {
    asm volatile(
        "mma.sync.aligned.m16n8k16.row.col.f32.bf16.bf16.f32 "
        "{%0,%1,%2,%3}, {%4,%5,%6,%7}, {%8,%9}, {%0,%1,%2,%3};"
        : "+f"(c[0]), "+f"(c[1]), "+f"(c[2]), "+f"(c[3])
        : "r"(a[0]), "r"(a[1]), "r"(a[2]), "r"(a[3]), "r"(b[0]), "r"(b[1]));
}
__device__ __forceinline__ void split_pack(float vx, float vy,
                                           uint32_t& hp, uint32_t& lp) {
    __nv_bfloat16 hx = __float2bfloat16_rn(vx);
    __nv_bfloat16 hy = __float2bfloat16_rn(vy);
    __nv_bfloat16 lx = __float2bfloat16_rn(vx - __bfloat162float(hx));
    __nv_bfloat16 ly = __float2bfloat16_rn(vy - __bfloat162float(hy));
    hp = (uint32_t)__bfloat16_as_ushort(hx)
       | ((uint32_t)__bfloat16_as_ushort(hy) << 16);
    lp = (uint32_t)__bfloat16_as_ushort(lx)
       | ((uint32_t)__bfloat16_as_ushort(ly) << 16);
}

// ---------------------------------------------------------------------------
// NCHW -> NHWC transpose of x
// ---------------------------------------------------------------------------
__global__ void transpose_x_kernel(const float* __restrict__ x) {
    __shared__ float tile[32][33];
    int b = blockIdx.z;
    int hw0 = blockIdx.x * 32;
    int c0 = blockIdx.y * 32;
    const float* xb = x + (size_t)b * C_IN * HW;
    #pragma unroll
    for (int i = threadIdx.y; i < 32; i += 8)
        tile[i][threadIdx.x] = xb[(size_t)(c0 + i) * HW + hw0 + threadIdx.x];
    __syncthreads();
    float* xt = g_xt + (size_t)b * HW * C_IN;
    #pragma unroll
    for (int i = threadIdx.y; i < 32; i += 8)
        xt[(size_t)(hw0 + i) * C_IN + c0 + threadIdx.x] = tile[threadIdx.x][i];
}

// ---------------------------------------------------------------------------
// Weight prep A: w_offset bf16 hi/lo -> [k][oc pad32][cin]
// ---------------------------------------------------------------------------
__global__ void prep_w_kernel(const float* __restrict__ wo) {
    int i = blockIdx.x * 256 + threadIdx.x;
    if (i < K2 * 32 * C_IN) {
        int c = i & 127;
        int oc = (i >> 7) & 31;
        int k = i >> 12;
        float v = (oc < 18) ? wo[(oc * 128 + c) * 9 + k] : 0.f;
        __nv_bfloat16 hi = __float2bfloat16_rn(v);
        __nv_bfloat16 lo = __float2bfloat16_rn(v - __bfloat162float(hi));
        g_woh[i] = hi;
        g_wol[i] = lo;
    }
}

// ---------------------------------------------------------------------------
// Weight prep B: w_conv -> mma B-fragment order, bf16 hi/lo pairs.
// Fragment for (tap t, o16-group g, k16 kc), lane l, mats m0..m3:
//   m0:(o=g*16+l/4,      k=kc*16+(l%4)*2)   m1:(same o, k+8)
//   m2:(o+8, k)                             m3:(o+8, k+8)
// Each u32 packs (W[o][k], W[o][k+1]).
// ---------------------------------------------------------------------------
__global__ void prep_wfrag_kernel(const float* __restrict__ wc) {
    int i = blockIdx.x * 256 + threadIdx.x;   // 0 .. 9*8*8*32-1
    if (i >= K2 * 8 * 8 * 32) return;
    int lane = i & 31;
    int kc = (i >> 5) & 7;
    int g = (i >> 8) & 7;
    int t = i >> 11;
    int ob = g * 16 + (lane >> 2);
    int kb = kc * 16 + (lane & 3) * 2;
    #pragma unroll
    for (int m = 0; m < 4; m++) {
        int o = ob + ((m >> 1) << 3);
        int k = kb + ((m & 1) << 3);
        float v0 = wc[(o * 128 + k) * 9 + t];
        float v1 = wc[(o * 128 + k + 1) * 9 + t];
        uint32_t hp, lp;
        split_pack(v0, v1, hp, lp);
        g_wfh[i * 4 + m] = hp;
        g_wfl[i * 4 + m] = lp;
    }
}

// ---------------------------------------------------------------------------
// Offset conv via tensor cores: M=128 px, N=32 (18 used), K=1152. (unchanged)
// ---------------------------------------------------------------------------
#define OSM_AHI 0u
#define OSM_ALO 32768u
#define OSM_WHI 65536u
#define OSM_WLO 73728u
#define OSMEM_BYTES 81920

__global__ __launch_bounds__(256, 2) void offset_mma() {
    extern __shared__ char smem[];
    const uint32_t sb = smem_u32(smem);
    const int tid = threadIdx.x;
    const int lane = tid & 31;
    const int wid = tid >> 5;
    const int b = blockIdx.x >> 5;
    const int pix0 = (blockIdx.x & 31) * 128;

    const float* xb = g_xt + (size_t)b * HW * C_IN;
    const uint32_t* whp = (const uint32_t*)g_woh;
    const uint32_t* wlp = (const uint32_t*)g_wol;

    float acc[4][4] = {};

    for (int k = 0; k < 9; k++) {
        int ky = k / 3 - 1, kx = k % 3 - 1;
        #pragma unroll
        for (int t = 0; t < 32; t++) {
            int idx = tid + 256 * t;
            int p = idx >> 6, j = idx & 63;
            int gp = pix0 + p;
            int y = (gp >> 6) + ky;
            int xx = (gp & 63) + kx;
            float2 v = make_float2(0.f, 0.f);
            if ((unsigned)y < 64u && (unsigned)xx < 64u)
                v = *(const float2*)&xb[(((y << 6) + xx) << 7) + 2 * j];
            uint32_t hp, lp;
            split_pack(v.x, v.y, hp, lp);
            uint32_t chunk = (uint32_t)(j >> 2);
            uint32_t sw = (uint32_t)p * 256u
                        + ((chunk ^ ((uint32_t)p & 7u)) << 4)
                        + ((uint32_t)(j & 3) << 2);
            *(uint32_t*)(smem + OSM_AHI + sw) = hp;
            *(uint32_t*)(smem + OSM_ALO + sw) = lp;
        }
        #pragma unroll
        for (int t = 0; t < 8; t++) {
            int idx = tid + 256 * t;
            int r = idx >> 6, j = idx & 63;
            uint32_t chunk = (uint32_t)(j >> 2);
            uint32_t sw = (uint32_t)r * 256u
                        + ((chunk ^ ((uint32_t)r & 7u)) << 4)
                        + ((uint32_t)(j & 3) << 2);
            int gi = (k * 32 + r) * 64 + j;
            *(uint32_t*)(smem + OSM_WHI + sw) = whp[gi];
            *(uint32_t*)(smem + OSM_WLO + sw) = wlp[gi];
        }
        __syncthreads();

        #pragma unroll
        for (int kc = 0; kc < 8; kc++) {
            uint32_t ah[4], al[4];
            int mat = lane >> 3;
            int arow = wid * 16 + (lane & 7) + ((mat & 1) << 3);
            int kcol = kc * 16 + ((mat >> 1) << 3);
            uint32_t chunk = (uint32_t)(kcol >> 3);
            uint32_t aoff = (uint32_t)arow * 256u
                          + ((chunk ^ ((uint32_t)arow & 7u)) << 4);
            ldsm_x4(ah, sb + OSM_AHI + aoff);
            ldsm_x4(al, sb + OSM_ALO + aoff);
            #pragma unroll
            for (int ng = 0; ng < 2; ng++) {
                int wrow = ng * 16 + (lane & 7) + ((lane >> 4) << 3);
                int kcol2 = kc * 16 + (((lane >> 3) & 1) << 3);
                uint32_t ch2 = (uint32_t)(kcol2 >> 3);
                uint32_t woff = (uint32_t)wrow * 256u
                              + ((ch2 ^ ((uint32_t)wrow & 7u)) << 4);
                uint32_t wh[4], wl[4];
                ldsm_x4(wh, sb + OSM_WHI + woff);
                ldsm_x4(wl, sb + OSM_WLO + woff);
                mma_bf16(acc[ng * 2 + 0], ah, wh + 0);
                mma_bf16(acc[ng * 2 + 1], ah, wh + 2);
                mma_bf16(acc[ng * 2 + 0], al, wh + 0);
                mma_bf16(acc[ng * 2 + 1], al, wh + 2);
                mma_bf16(acc[ng * 2 + 0], ah, wl + 0);
                mma_bf16(acc[ng * 2 + 1], ah, wl + 2);
            }
        }
        __syncthreads();
    }

    int px0 = pix0 + wid * 16 + (lane >> 2);
    #pragma unroll
    for (int nt = 0; nt < 4; nt++) {
        int ch = nt * 8 + (lane & 3) * 2;
        if (ch < 18) {
            float* op = g_off + ((size_t)b * 18 + ch) * HW;
            op[px0]       = acc[nt][0];
            op[HW + px0]  = acc[nt][1];
            op[px0 + 8]      = acc[nt][2];
            op[HW + px0 + 8] = acc[nt][3];
        }
    }
}

// ---------------------------------------------------------------------------
// Deformable conv, half-K software pipeline:
//   iteration hh (18 halves of 64 cin): gather A(hh+1) into buf[(hh+1)&1],
//   then MMA half hh from buf[hh&1] with W fragments LDG'd from global.
//   One __syncthreads per half. cw/coff double-buffered by tap parity.
// A half buffer row (per px): 256B = [64 cin hi (128B) | 64 cin lo (128B)],
// 16B chunks XOR-swizzled by (px & 7).
// SMEM (73728 B): A0[0,32K) A1[32K,64K) cw[64K,+4K) coff[68K,+4K)
// ---------------------------------------------------------------------------
#define DSM_A0 0u
#define DSM_A1 32768u
#define DSM_CW 65536u
#define DSM_CO 69632u
#define DSMEM_BYTES 73728

__global__ __launch_bounds__(256, 2) void deform_mma(float* __restrict__ out) {
    extern __shared__ char smem[];
    const uint32_t sb = smem_u32(smem);
    const int tid = threadIdx.x;
    const int lane = tid & 31;
    const int wid = tid >> 5;
    const int b = blockIdx.x >> 5;
    const int pix0 = (blockIdx.x & 31) * 128;

    const int wy = wid & 3;          // px group: 32 px
    const int wx = wid >> 2;         // out group: 64 o

    float* cwbuf = (float*)(smem + DSM_CW);   // [par][j*128+p]
    int* cobuf = (int*)(smem + DSM_CO);
    const float* xb = g_xt + (size_t)b * HW * C_IN;

    float acc[2][8][4] = {};

    // --- per-tap bilinear setup into parity buffer (1 thread/pixel) ---
    auto tap_setup = [&](int tap) {
        if (tid < 128) {
            int p = tid;
            int par = tap & 1;
            int gp = pix0 + p;
            int h = gp >> 6, w = gp & 63;
            float dy = g_off[((b * 18 + 2 * tap) * 64 + h) * 64 + w];
            float dx = g_off[((b * 18 + 2 * tap + 1) * 64 + h) * 64 + w];
            float py = (float)(h - 1 + tap / 3) + dy;
            float px = (float)(w - 1 + tap % 3) + dx;
            float y0f = floorf(py), x0f = floorf(px);
            float fy = py - y0f, fx = px - x0f;
            #pragma unroll
            for (int j = 0; j < 4; j++) {
                float yf = y0f + (float)(j >> 1);
                float xf = x0f + (float)(j & 1);
                bool ok = (yf >= 0.f && yf < 64.f && xf >= 0.f && xf < 64.f);
                float wy_ = (j >> 1) ? fy : 1.f - fy;
                float wx_ = (j & 1) ? fx : 1.f - fx;
                cwbuf[par * 512 + j * 128 + p] = ok ? wy_ * wx_ : 0.f;
                int yi = (int)fminf(fmaxf(yf, 0.f), 63.f);
                int xi = (int)fminf(fmaxf(xf, 0.f), 63.f);
                cobuf[par * 512 + j * 128 + p] = ((yi << 6) + xi) << 7;
            }
        }
    };

    // --- gather one half (64 cin) into its A buffer ---
    auto gather_half = [&](int hh2) {
        int par = (hh2 >> 1) & 1;
        int c0 = (hh2 & 1) * 64;
        char* ab = smem + ((hh2 & 1) ? DSM_A1 : DSM_A0);
        const float* cw = cwbuf + par * 512;
        const int* co = cobuf + par * 512;
        #pragma unroll 4
        for (int i = 0; i < 16; i++) {
            int p = wid * 16 + i;
            float w0 = cw[p], w1 = cw[128 + p];
            float w2 = cw[256 + p], w3 = cw[384 + p];
            int o0 = co[p], o1 = co[128 + p];
            int o2 = co[256 + p], o3 = co[384 + p];
            float vx = 0.f, vy = 0.f;
            const float* base = xb + c0 + 2 * lane;
            if (w0 != 0.f) { float2 t = *(const float2*)(base + o0); vx += w0 * t.x; vy += w0 * t.y; }
            if (w1 != 0.f) { float2 t = *(const float2*)(base + o1); vx += w1 * t.x; vy += w1 * t.y; }
            if (w2 != 0.f) { float2 t = *(const float2*)(base + o2); vx += w2 * t.x; vy += w2 * t.y; }
            if (w3 != 0.f) { float2 t = *(const float2*)(base + o3); vx += w3 * t.x; vy += w3 * t.y; }
            uint32_t hp, lp;
            split_pack(vx, vy, hp, lp);
            uint32_t sw = (uint32_t)p * 256u
                        + ((((uint32_t)lane >> 2) ^ ((uint32_t)p & 7u)) << 4)
                        + (((uint32_t)lane & 3u) << 2);
            *(uint32_t*)(ab + sw) = hp;
            *(uint32_t*)(ab + sw + 128) = lp;
        }
    };

    // --- prologue: setup tap 0, gather half 0 ---
    tap_setup(0);
    __syncthreads();
    gather_half(0);
    __syncthreads();

    for (int hh = 0; hh < 18; hh++) {
        int tap = hh >> 1;
        int half = hh & 1;

        // overlap: next-tap setup + next-half gather before this half's MMA
        if (half == 0 && tap + 1 < 9) tap_setup(tap + 1);
        if (hh + 1 < 18) gather_half(hh + 1);

        // --- MMA this half: A from smem buffer, W frags from global ---
        uint32_t abu = sb + (half ? DSM_A1 : DSM_A0);
        #pragma unroll
        for (int kc = 0; kc < 4; kc++) {
            uint32_t ah[2][4], al[2][4];
            #pragma unroll
            for (int mt = 0; mt < 2; mt++) {
                int mat = lane >> 3;
                int arow = wy * 32 + mt * 16 + (lane & 7) + ((mat & 1) << 3);
                int kcol = kc * 16 + ((mat >> 1) << 3);
                uint32_t c = (uint32_t)(kcol >> 3);
                uint32_t aoff = (uint32_t)arow * 256u
                              + ((c ^ ((uint32_t)arow & 7u)) << 4);
                ldsm_x4(ah[mt], abu + aoff);
                ldsm_x4(al[mt], abu + aoff + 128);
            }
            #pragma unroll
            for (int ng = 0; ng < 4; ng++) {
                int g = wx * 4 + ng;
                size_t fi = ((((size_t)tap * 8 + g) * 8 + half * 4 + kc) * 32
                             + lane) * 4;
                uint4 whf = *(const uint4*)(g_wfh + fi);
                uint4 wlf = *(const uint4*)(g_wfl + fi);
                uint32_t bh[4] = {whf.x, whf.y, whf.z, whf.w};
                uint32_t bl[4] = {wlf.x, wlf.y, wlf.z, wlf.w};
                #pragma unroll
                for (int mt = 0; mt < 2; mt++) {
                    mma_bf16(acc[mt][ng * 2 + 0], ah[mt], bh + 0);
                    mma_bf16(acc[mt][ng * 2 + 1], ah[mt], bh + 2);
                    mma_bf16(acc[mt][ng * 2 + 0], al[mt], bh + 0);
                    mma_bf16(acc[mt][ng * 2 + 1], al[mt], bh + 2);
                    mma_bf16(acc[mt][ng * 2 + 0], ah[mt], bl + 0);
                    mma_bf16(acc[mt][ng * 2 + 1], ah[mt], bl + 2);
                }
            }
        }
        __syncthreads();
    }

    // --- epilogue: c-frag -> out[b][o][px] ---
    float* ob = out + (size_t)b * 128 * HW;
    #pragma unroll
    for (int mt = 0; mt < 2; mt++) {
        int px0 = pix0 + wy * 32 + mt * 16 + (lane >> 2);
        #pragma unroll
        for (int nt = 0; nt < 8; nt++) {
            int o = wx * 64 + nt * 8 + (lane & 3) * 2;
            ob[(size_t)o * HW + px0]            = acc[mt][nt][0];
            ob[(size_t)(o + 1) * HW + px0]      = acc[mt][nt][1];
            ob[(size_t)o * HW + px0 + 8]        = acc[mt][nt][2];
            ob[(size_t)(o + 1) * HW + px0 + 8]  = acc[mt][nt][3];
        }
    }
}

// ---------------------------------------------------------------------------
extern "C" void kernel_launch(void* const* d_in, const int* in_sizes, int n_in,
                              void* d_out, int out_size) {
    const float* x  = (const float*)d_in[0];
    const float* wo = (const float*)d_in[1];   // w_offset
    const float* wc = (const float*)d_in[2];   // w_conv
    float* out = (float*)d_out;

    static bool attr_set = false;
    if (!attr_set) {
        cudaFuncSetAttribute(deform_mma,
                             cudaFuncAttributeMaxDynamicSharedMemorySize,
                             DSMEM_BYTES);
        cudaFuncSetAttribute(offset_mma,
                             cudaFuncAttributeMaxDynamicSharedMemorySize,
                             OSMEM_BYTES);
        attr_set = true;
    }

    dim3 tpb(32, 8);
    transpose_x_kernel<<<dim3(HW / 32, C_IN / 32, Bn), tpb>>>(x);
    prep_w_kernel<<<(K2 * 32 * C_IN + 255) / 256, 256>>>(wo);
    prep_wfrag_kernel<<<(K2 * 8 * 8 * 32 + 255) / 256, 256>>>(wc);
    offset_mma<<<Bn * (HW / 128), 256, OSMEM_BYTES>>>();
    deform_mma<<<Bn * (HW / 128), 256, DSMEM_BYTES>>>(out);
}

// round 10
// speedup vs baseline: 3.0491x; 1.0962x over previous
#include <cuda_runtime.h>
#include <cuda_bf16.h>
#include <cstdint>

#define Bn 8
#define C_IN 128
#define C_OUT 128
#define K2 9
#define HH 64
#define WW 64
#define HW 4096
#define NOFF 18

// Scratch (no cudaMalloc allowed)
__device__ float g_xt[Bn * HW * C_IN];            // x NHWC fp32: [b][y][x][c]
__device__ __nv_bfloat16 g_xbh[Bn * HW * C_IN];   // x NHWC bf16 hi
__device__ __nv_bfloat16 g_xbl[Bn * HW * C_IN];   // x NHWC bf16 lo
__device__ float g_off[Bn * NOFF * HW];           // offsets: [b][ch][y][x]
// w_conv in mma B-fragment order: [tap][o16-group(8)][k16(8)][lane(32)][mat(4)]
__device__ uint32_t g_wfh[K2 * 8 * 8 * 32 * 4];   // hi pairs
__device__ uint32_t g_wfl[K2 * 8 * 8 * 32 * 4];   // lo pairs
// w_offset frags: [tap][ng(2)][k16(8)][lane(32)][mat(4)]
__device__ uint32_t g_wofh[K2 * 2 * 8 * 32 * 4];
__device__ uint32_t g_wofl[K2 * 2 * 8 * 32 * 4];

// ---------------------------------------------------------------------------
// Helpers (portable PTX: ldmatrix + mma.sync + cp.async, sm_80+)
// ---------------------------------------------------------------------------
__device__ __forceinline__ uint32_t smem_u32(const void* p) {
    uint32_t a;
    asm("{ .reg .u64 t; cvta.to.shared.u64 t, %1; cvt.u32.u64 %0, t; }"
        : "=r"(a) : "l"(p));
    return a;
}
__device__ __forceinline__ void ldsm_x4(uint32_t* r, uint32_t addr) {
    asm volatile("ldmatrix.sync.aligned.m8n8.x4.shared.b16 {%0,%1,%2,%3}, [%4];"
                 : "=r"(r[0]), "=r"(r[1]), "=r"(r[2]), "=r"(r[3]) : "r"(addr));
}
__device__ __forceinline__ void mma_bf16(float* c, const uint32_t* a,
                                         const uint32_t* b) {
    asm volatile(
        "mma.sync.aligned.m16n8k16.row.col.f32.bf16.bf16.f32 "
        "{%0,%1,%2,%3}, {%4,%5,%6,%7}, {%8,%9}, {%0,%1,%2,%3};"
        : "+f"(c[0]), "+f"(c[1]), "+f"(c[2]), "+f"(c[3])
        : "r"(a[0]), "r"(a[1]), "r"(a[2]), "r"(a[3]), "r"(b[0]), "r"(b[1]));
}
__device__ __forceinline__ void split_pack(float vx, float vy,
                                           uint32_t& hp, uint32_t& lp) {
    __nv_bfloat16 hx = __float2bfloat16_rn(vx);
    __nv_bfloat16 hy = __float2bfloat16_rn(vy);
    __nv_bfloat16 lx = __float2bfloat16_rn(vx - __bfloat162float(hx));
    __nv_bfloat16 ly = __float2bfloat16_rn(vy - __bfloat162float(hy));
    hp = (uint32_t)__bfloat16_as_ushort(hx)
       | ((uint32_t)__bfloat16_as_ushort(hy) << 16);
    lp = (uint32_t)__bfloat16_as_ushort(lx)
       | ((uint32_t)__bfloat16_as_ushort(ly) << 16);
}
__device__ __forceinline__ void cp_async16(uint32_t dst, const void* src,
                                           int srcsize) {
    asm volatile("cp.async.cg.shared.global [%0], [%1], 16, %2;"
                 :: "r"(dst), "l"(src), "r"(srcsize) : "memory");
}
#define CP_COMMIT() asm volatile("cp.async.commit_group;" ::: "memory")
#define CP_WAIT0()  asm volatile("cp.async.wait_group 0;" ::: "memory")

// ---------------------------------------------------------------------------
// NCHW -> NHWC transpose of x, fused with bf16 hi/lo split
// ---------------------------------------------------------------------------
__global__ void transpose_x_kernel(const float* __restrict__ x) {
    __shared__ float tile[32][33];
    int b = blockIdx.z;
    int hw0 = blockIdx.x * 32;
    int c0 = blockIdx.y * 32;
    const float* xb = x + (size_t)b * C_IN * HW;
    #pragma unroll
    for (int i = threadIdx.y; i < 32; i += 8)
        tile[i][threadIdx.x] = xb[(size_t)(c0 + i) * HW + hw0 + threadIdx.x];
    __syncthreads();
    size_t base = (size_t)b * HW * C_IN;
    #pragma unroll
    for (int i = threadIdx.y; i < 32; i += 8) {
        float v = tile[threadIdx.x][i];
        size_t idx = base + (size_t)(hw0 + i) * C_IN + c0 + threadIdx.x;
        g_xt[idx] = v;
        __nv_bfloat16 hi = __float2bfloat16_rn(v);
        g_xbh[idx] = hi;
        g_xbl[idx] = __float2bfloat16_rn(v - __bfloat162float(hi));
    }
}

// ---------------------------------------------------------------------------
// Weight prep: w_conv -> deform mma B-fragment order (unchanged layout)
// ---------------------------------------------------------------------------
__global__ void prep_wfrag_kernel(const float* __restrict__ wc) {
    int i = blockIdx.x * 256 + threadIdx.x;   // 0 .. 9*8*8*32-1
    if (i >= K2 * 8 * 8 * 32) return;
    int lane = i & 31;
    int kc = (i >> 5) & 7;
    int g = (i >> 8) & 7;
    int t = i >> 11;
    int ob = g * 16 + (lane >> 2);
    int kb = kc * 16 + (lane & 3) * 2;
    #pragma unroll
    for (int m = 0; m < 4; m++) {
        int o = ob + ((m >> 1) << 3);
        int k = kb + ((m & 1) << 3);
        float v0 = wc[(o * 128 + k) * 9 + t];
        float v1 = wc[(o * 128 + k + 1) * 9 + t];
        uint32_t hp, lp;
        split_pack(v0, v1, hp, lp);
        g_wfh[i * 4 + m] = hp;
        g_wfl[i * 4 + m] = lp;
    }
}

// ---------------------------------------------------------------------------
// Weight prep: w_offset -> mma B-fragment order [t][ng(2)][k16(8)][lane][4]
// (oc padded to 32 with zeros)
// ---------------------------------------------------------------------------
__global__ void prep_wofrag_kernel(const float* __restrict__ wo) {
    int i = blockIdx.x * 256 + threadIdx.x;   // 0 .. 9*2*8*32-1
    if (i >= K2 * 2 * 8 * 32) return;
    int lane = i & 31;
    int kc8 = (i >> 5) & 7;
    int ng = (i >> 8) & 1;
    int t = i >> 9;
    #pragma unroll
    for (int m = 0; m < 4; m++) {
        int o = ng * 16 + (lane >> 2) + ((m >> 1) << 3);
        int k = kc8 * 16 + (lane & 3) * 2 + ((m & 1) << 3);
        float v0 = (o < 18) ? wo[(o * 128 + k) * 9 + t] : 0.f;
        float v1 = (o < 18) ? wo[(o * 128 + k + 1) * 9 + t] : 0.f;
        uint32_t hp, lp;
        split_pack(v0, v1, hp, lp);
        g_wofh[i * 4 + m] = hp;
        g_wofl[i * 4 + m] = lp;
    }
}

// ---------------------------------------------------------------------------
// Offset conv, cp.async pipeline: M=128 px, N=32 (18 used), K=1152.
// 18 halves (tap x 64cin). A staged by cp.async from pre-split bf16 x
// (zero-fill for OOB), double-buffered; W frags LDG'd from global.
// Buffer row (px): 256B = [64cin hi | 64cin lo], 16B chunks XOR-swizzled.
// SMEM: A0[0,32K) A1[32K,64K)
// ---------------------------------------------------------------------------
#define OSM_A0 0u
#define OSM_A1 32768u
#define OSMEM_BYTES 65536

__global__ __launch_bounds__(256, 2) void offset_mma() {
    extern __shared__ char smem[];
    const uint32_t sb = smem_u32(smem);
    const int tid = threadIdx.x;
    const int lane = tid & 31;
    const int wid = tid >> 5;
    const int b = blockIdx.x >> 5;
    const int pix0 = (blockIdx.x & 31) * 128;

    float acc[4][4] = {};

    auto stage = [&](int hh) {
        int tap = hh >> 1;
        int c0 = (hh & 1) * 64;
        int ky = tap / 3 - 1, kx = tap % 3 - 1;
        uint32_t ab = sb + ((hh & 1) ? OSM_A1 : OSM_A0);
        #pragma unroll
        for (int q = 0; q < 8; q++) {
            int cid = tid + 256 * q;
            int p = cid >> 4, sub = cid & 15;
            int cc = sub & 7;
            int gp = pix0 + p;
            int y = (gp >> 6) + ky;
            int xx = (gp & 63) + kx;
            bool ok = ((unsigned)y < 64u) && ((unsigned)xx < 64u);
            const __nv_bfloat16* sp = (sub < 8 ? g_xbh : g_xbl)
                + ((size_t)b * HW + (ok ? ((y << 6) + xx) : 0)) * 128
                + c0 + cc * 8;
            uint32_t dst = ab + (uint32_t)p * 256u
                         + ((uint32_t)(cc ^ (p & 7)) << 4)
                         + (sub < 8 ? 0u : 128u);
            cp_async16(dst, sp, ok ? 16 : 0);
        }
    };

    stage(0);
    CP_COMMIT();

    for (int hh = 0; hh < 18; hh++) {
        CP_WAIT0();
        __syncthreads();           // buf[hh&1] complete block-wide; prev MMA done
        if (hh + 1 < 18) { stage(hh + 1); CP_COMMIT(); }

        int tap = hh >> 1, half = hh & 1;
        uint32_t abu = sb + (half ? OSM_A1 : OSM_A0);
        #pragma unroll
        for (int kc = 0; kc < 4; kc++) {
            uint32_t ah[4], al[4];
            int mat = lane >> 3;
            int arow = wid * 16 + (lane & 7) + ((mat & 1) << 3);
            int kcol = kc * 16 + ((mat >> 1) << 3);
            uint32_t c = (uint32_t)(kcol >> 3);
            uint32_t aoff = (uint32_t)arow * 256u
                          + ((c ^ ((uint32_t)arow & 7u)) << 4);
            ldsm_x4(ah, abu + aoff);
            ldsm_x4(al, abu + aoff + 128);
            #pragma unroll
            for (int ng = 0; ng < 2; ng++) {
                size_t fi = ((((size_t)tap * 2 + ng) * 8 + half * 4 + kc) * 32
                             + lane) * 4;
                uint4 whf = *(const uint4*)(g_wofh + fi);
                uint4 wlf = *(const uint4*)(g_wofl + fi);
                uint32_t bh[4] = {whf.x, whf.y, whf.z, whf.w};
                uint32_t bl[4] = {wlf.x, wlf.y, wlf.z, wlf.w};
                mma_bf16(acc[ng * 2 + 0], ah, bh + 0);
                mma_bf16(acc[ng * 2 + 1], ah, bh + 2);
                mma_bf16(acc[ng * 2 + 0], al, bh + 0);
                mma_bf16(acc[ng * 2 + 1], al, bh + 2);
                mma_bf16(acc[ng * 2 + 0], ah, bl + 0);
                mma_bf16(acc[ng * 2 + 1], ah, bl + 2);
            }
        }
    }

    int px0 = pix0 + wid * 16 + (lane >> 2);
    #pragma unroll
    for (int nt = 0; nt < 4; nt++) {
        int ch = nt * 8 + (lane & 3) * 2;
        if (ch < 18) {
            float* op = g_off + ((size_t)b * 18 + ch) * HW;
            op[px0]       = acc[nt][0];
            op[HW + px0]  = acc[nt][1];
            op[px0 + 8]      = acc[nt][2];
            op[HW + px0 + 8] = acc[nt][3];
        }
    }
}

// ---------------------------------------------------------------------------
// Deformable conv, half-K software pipeline (unchanged from R9).
// SMEM (73728 B): A0[0,32K) A1[32K,64K) cw[64K,+4K) coff[68K,+4K)
// ---------------------------------------------------------------------------
#define DSM_A0 0u
#define DSM_A1 32768u
#define DSM_CW 65536u
#define DSM_CO 69632u
#define DSMEM_BYTES 73728

__global__ __launch_bounds__(256, 2) void deform_mma(float* __restrict__ out) {
    extern __shared__ char smem[];
    const uint32_t sb = smem_u32(smem);
    const int tid = threadIdx.x;
    const int lane = tid & 31;
    const int wid = tid >> 5;
    const int b = blockIdx.x >> 5;
    const int pix0 = (blockIdx.x & 31) * 128;

    const int wy = wid & 3;          // px group: 32 px
    const int wx = wid >> 2;         // out group: 64 o

    float* cwbuf = (float*)(smem + DSM_CW);   // [par][j*128+p]
    int* cobuf = (int*)(smem + DSM_CO);
    const float* xb = g_xt + (size_t)b * HW * C_IN;

    float acc[2][8][4] = {};

    auto tap_setup = [&](int tap) {
        if (tid < 128) {
            int p = tid;
            int par = tap & 1;
            int gp = pix0 + p;
            int h = gp >> 6, w = gp & 63;
            float dy = g_off[((b * 18 + 2 * tap) * 64 + h) * 64 + w];
            float dx = g_off[((b * 18 + 2 * tap + 1) * 64 + h) * 64 + w];
            float py = (float)(h - 1 + tap / 3) + dy;
            float px = (float)(w - 1 + tap % 3) + dx;
            float y0f = floorf(py), x0f = floorf(px);
            float fy = py - y0f, fx = px - x0f;
            #pragma unroll
            for (int j = 0; j < 4; j++) {
                float yf = y0f + (float)(j >> 1);
                float xf = x0f + (float)(j & 1);
                bool ok = (yf >= 0.f && yf < 64.f && xf >= 0.f && xf < 64.f);
                float wy_ = (j >> 1) ? fy : 1.f - fy;
                float wx_ = (j & 1) ? fx : 1.f - fx;
                cwbuf[par * 512 + j * 128 + p] = ok ? wy_ * wx_ : 0.f;
                int yi = (int)fminf(fmaxf(yf, 0.f), 63.f);
                int xi = (int)fminf(fmaxf(xf, 0.f), 63.f);
                cobuf[par * 512 + j * 128 + p] = ((yi << 6) + xi) << 7;
            }
        }
    };

    auto gather_half = [&](int hh2) {
        int par = (hh2 >> 1) & 1;
        int c0 = (hh2 & 1) * 64;
        char* ab = smem + ((hh2 & 1) ? DSM_A1 : DSM_A0);
        const float* cw = cwbuf + par * 512;
        const int* co = cobuf + par * 512;
        #pragma unroll 4
        for (int i = 0; i < 16; i++) {
            int p = wid * 16 + i;
            float w0 = cw[p], w1 = cw[128 + p];
            float w2 = cw[256 + p], w3 = cw[384 + p];
            int o0 = co[p], o1 = co[128 + p];
            int o2 = co[256 + p], o3 = co[384 + p];
            float vx = 0.f, vy = 0.f;
            const float* base = xb + c0 + 2 * lane;
            if (w0 != 0.f) { float2 t = *(const float2*)(base + o0); vx += w0 * t.x; vy += w0 * t.y; }
            if (w1 != 0.f) { float2 t = *(const float2*)(base + o1); vx += w1 * t.x; vy += w1 * t.y; }
            if (w2 != 0.f) { float2 t = *(const float2*)(base + o2); vx += w2 * t.x; vy += w2 * t.y; }
            if (w3 != 0.f) { float2 t = *(const float2*)(base + o3); vx += w3 * t.x; vy += w3 * t.y; }
            uint32_t hp, lp;
            split_pack(vx, vy, hp, lp);
            uint32_t sw = (uint32_t)p * 256u
                        + ((((uint32_t)lane >> 2) ^ ((uint32_t)p & 7u)) << 4)
                        + (((uint32_t)lane & 3u) << 2);
            *(uint32_t*)(ab + sw) = hp;
            *(uint32_t*)(ab + sw + 128) = lp;
        }
    };

    tap_setup(0);
    __syncthreads();
    gather_half(0);
    __syncthreads();

    for (int hh = 0; hh < 18; hh++) {
        int tap = hh >> 1;
        int half = hh & 1;

        if (half == 0 && tap + 1 < 9) tap_setup(tap + 1);
        if (hh + 1 < 18) gather_half(hh + 1);

        uint32_t abu = sb + (half ? DSM_A1 : DSM_A0);
        #pragma unroll
        for (int kc = 0; kc < 4; kc++) {
            uint32_t ah[2][4], al[2][4];
            #pragma unroll
            for (int mt = 0; mt < 2; mt++) {
                int mat = lane >> 3;
                int arow = wy * 32 + mt * 16 + (lane & 7) + ((mat & 1) << 3);
                int kcol = kc * 16 + ((mat >> 1) << 3);
                uint32_t c = (uint32_t)(kcol >> 3);
                uint32_t aoff = (uint32_t)arow * 256u
                              + ((c ^ ((uint32_t)arow & 7u)) << 4);
                ldsm_x4(ah[mt], abu + aoff);
                ldsm_x4(al[mt], abu + aoff + 128);
            }
            #pragma unroll
            for (int ng = 0; ng < 4; ng++) {
                int g = wx * 4 + ng;
                size_t fi = ((((size_t)tap * 8 + g) * 8 + half * 4 + kc) * 32
                             + lane) * 4;
                uint4 whf = *(const uint4*)(g_wfh + fi);
                uint4 wlf = *(const uint4*)(g_wfl + fi);
                uint32_t bh[4] = {whf.x, whf.y, whf.z, whf.w};
                uint32_t bl[4] = {wlf.x, wlf.y, wlf.z, wlf.w};
                #pragma unroll
                for (int mt = 0; mt < 2; mt++) {
                    mma_bf16(acc[mt][ng * 2 + 0], ah[mt], bh + 0);
                    mma_bf16(acc[mt][ng * 2 + 1], ah[mt], bh + 2);
                    mma_bf16(acc[mt][ng * 2 + 0], al[mt], bh + 0);
                    mma_bf16(acc[mt][ng * 2 + 1], al[mt], bh + 2);
                    mma_bf16(acc[mt][ng * 2 + 0], ah[mt], bl + 0);
                    mma_bf16(acc[mt][ng * 2 + 1], ah[mt], bl + 2);
                }
            }
        }
        __syncthreads();
    }

    float* ob = out + (size_t)b * 128 * HW;
    #pragma unroll
    for (int mt = 0; mt < 2; mt++) {
        int px0 = pix0 + wy * 32 + mt * 16 + (lane >> 2);
        #pragma unroll
        for (int nt = 0; nt < 8; nt++) {
            int o = wx * 64 + nt * 8 + (lane & 3) * 2;
            ob[(size_t)o * HW + px0]            = acc[mt][nt][0];
            ob[(size_t)(o + 1) * HW + px0]      = acc[mt][nt][1];
            ob[(size_t)o * HW + px0 + 8]        = acc[mt][nt][2];
            ob[(size_t)(o + 1) * HW + px0 + 8]  = acc[mt][nt][3];
        }
    }
}

// ---------------------------------------------------------------------------
extern "C" void kernel_launch(void* const* d_in, const int* in_sizes, int n_in,
                              void* d_out, int out_size) {
    const float* x  = (const float*)d_in[0];
    const float* wo = (const float*)d_in[1];   // w_offset
    const float* wc = (const float*)d_in[2];   // w_conv
    float* out = (float*)d_out;

    static bool attr_set = false;
    if (!attr_set) {
        cudaFuncSetAttribute(deform_mma,
                             cudaFuncAttributeMaxDynamicSharedMemorySize,
                             DSMEM_BYTES);
        cudaFuncSetAttribute(offset_mma,
                             cudaFuncAttributeMaxDynamicSharedMemorySize,
                             OSMEM_BYTES);
        attr_set = true;
    }

    dim3 tpb(32, 8);
    transpose_x_kernel<<<dim3(HW / 32, C_IN / 32, Bn), tpb>>>(x);
    prep_wfrag_kernel<<<(K2 * 8 * 8 * 32 + 255) / 256, 256>>>(wc);
    prep_wofrag_kernel<<<(K2 * 2 * 8 * 32 + 255) / 256, 256>>>(wo);
    offset_mma<<<Bn * (HW / 128), 256, OSMEM_BYTES>>>();
    deform_mma<<<Bn * (HW / 128), 256, DSMEM_BYTES>>>(out);
}

// round 11
// speedup vs baseline: 3.2010x; 1.0498x over previous
#include <cuda_runtime.h>
#include <cuda_bf16.h>
#include <cstdint>

#define Bn 8
#define C_IN 128
#define C_OUT 128
#define K2 9
#define HH 64
#define WW 64
#define HW 4096
#define NOFF 18

// Scratch (no cudaMalloc allowed)
__device__ float g_xt[Bn * HW * C_IN];            // x NHWC fp32: [b][y][x][c]
__device__ __nv_bfloat16 g_xbh[Bn * HW * C_IN];   // x NHWC bf16 hi
__device__ __nv_bfloat16 g_xbl[Bn * HW * C_IN];   // x NHWC bf16 lo
// w_conv in mma B-fragment order: [tap][o16-group(8)][k16(8)][lane(32)][mat(4)]
__device__ uint32_t g_wfh[K2 * 8 * 8 * 32 * 4];   // hi pairs
__device__ uint32_t g_wfl[K2 * 8 * 8 * 32 * 4];   // lo pairs
// w_offset frags: [tap][ng(2)][k16(8)][lane(32)][mat(4)]
__device__ uint32_t g_wofh[K2 * 2 * 8 * 32 * 4];
__device__ uint32_t g_wofl[K2 * 2 * 8 * 32 * 4];

// ---------------------------------------------------------------------------
// Helpers (portable PTX: ldmatrix + mma.sync + cp.async, sm_80+)
// ---------------------------------------------------------------------------
__device__ __forceinline__ uint32_t smem_u32(const void* p) {
    uint32_t a;
    asm("{ .reg .u64 t; cvta.to.shared.u64 t, %1; cvt.u32.u64 %0, t; }"
        : "=r"(a) : "l"(p));
    return a;
}
__device__ __forceinline__ void ldsm_x4(uint32_t* r, uint32_t addr) {
    asm volatile("ldmatrix.sync.aligned.m8n8.x4.shared.b16 {%0,%1,%2,%3}, [%4];"
                 : "=r"(r[0]), "=r"(r[1]), "=r"(r[2]), "=r"(r[3]) : "r"(addr));
}
__device__ __forceinline__ void mma_bf16(float* c, const uint32_t* a,
                                         const uint32_t* b) {
    asm volatile(
        "mma.sync.aligned.m16n8k16.row.col.f32.bf16.bf16.f32 "
        "{%0,%1,%2,%3}, {%4,%5,%6,%7}, {%8,%9}, {%0,%1,%2,%3};"
        : "+f"(c[0]), "+f"(c[1]), "+f"(c[2]), "+f"(c[3])
        : "r"(a[0]), "r"(a[1]), "r"(a[2]), "r"(a[3]), "r"(b[0]), "r"(b[1]));
}
// hi = rn(v), lo = rn(v - float(hi)) for a pair (vx, vy); packed bf16x2.
// Fast form: 2x cvt.rn.bf16x2 + SHF/LOP + 2 FADD. Bit-identical to the
// scalar __float2bfloat16_rn construction.
__device__ __forceinline__ void split_pack(float vx, float vy,
                                           uint32_t& hp, uint32_t& lp) {
    asm("cvt.rn.bf16x2.f32 %0, %1, %2;" : "=r"(hp) : "f"(vy), "f"(vx));
    float hxf = __uint_as_float(hp << 16);
    float hyf = __uint_as_float(hp & 0xFFFF0000u);
    float rx = vx - hxf;
    float ry = vy - hyf;
    asm("cvt.rn.bf16x2.f32 %0, %1, %2;" : "=r"(lp) : "f"(ry), "f"(rx));
}
__device__ __forceinline__ void split_pack_s(float vx, float vy,
                                             uint32_t& hp, uint32_t& lp) {
    __nv_bfloat16 hx = __float2bfloat16_rn(vx);
    __nv_bfloat16 hy = __float2bfloat16_rn(vy);
    __nv_bfloat16 lx = __float2bfloat16_rn(vx - __bfloat162float(hx));
    __nv_bfloat16 ly = __float2bfloat16_rn(vy - __bfloat162float(hy));
    hp = (uint32_t)__bfloat16_as_ushort(hx)
       | ((uint32_t)__bfloat16_as_ushort(hy) << 16);
    lp = (uint32_t)__bfloat16_as_ushort(lx)
       | ((uint32_t)__bfloat16_as_ushort(ly) << 16);
}
__device__ __forceinline__ void cp_async16(uint32_t dst, const void* src,
                                           int srcsize) {
    asm volatile("cp.async.cg.shared.global [%0], [%1], 16, %2;"
                 :: "r"(dst), "l"(src), "r"(srcsize) : "memory");
}
#define CP_COMMIT() asm volatile("cp.async.commit_group;" ::: "memory")
#define CP_WAIT0()  asm volatile("cp.async.wait_group 0;" ::: "memory")

// ---------------------------------------------------------------------------
// NCHW -> NHWC transpose of x, fused with bf16 hi/lo split
// ---------------------------------------------------------------------------
__global__ void transpose_x_kernel(const float* __restrict__ x) {
    __shared__ float tile[32][33];
    int b = blockIdx.z;
    int hw0 = blockIdx.x * 32;
    int c0 = blockIdx.y * 32;
    const float* xb = x + (size_t)b * C_IN * HW;
    #pragma unroll
    for (int i = threadIdx.y; i < 32; i += 8)
        tile[i][threadIdx.x] = xb[(size_t)(c0 + i) * HW + hw0 + threadIdx.x];
    __syncthreads();
    size_t base = (size_t)b * HW * C_IN;
    #pragma unroll
    for (int i = threadIdx.y; i < 32; i += 8) {
        float v = tile[threadIdx.x][i];
        size_t idx = base + (size_t)(hw0 + i) * C_IN + c0 + threadIdx.x;
        g_xt[idx] = v;
        __nv_bfloat16 hi = __float2bfloat16_rn(v);
        g_xbh[idx] = hi;
        g_xbl[idx] = __float2bfloat16_rn(v - __bfloat162float(hi));
    }
}

// ---------------------------------------------------------------------------
// Weight prep: w_conv -> deform mma B-fragment order
// ---------------------------------------------------------------------------
__global__ void prep_wfrag_kernel(const float* __restrict__ wc) {
    int i = blockIdx.x * 256 + threadIdx.x;   // 0 .. 9*8*8*32-1
    if (i >= K2 * 8 * 8 * 32) return;
    int lane = i & 31;
    int kc = (i >> 5) & 7;
    int g = (i >> 8) & 7;
    int t = i >> 11;
    int ob = g * 16 + (lane >> 2);
    int kb = kc * 16 + (lane & 3) * 2;
    #pragma unroll
    for (int m = 0; m < 4; m++) {
        int o = ob + ((m >> 1) << 3);
        int k = kb + ((m & 1) << 3);
        float v0 = wc[(o * 128 + k) * 9 + t];
        float v1 = wc[(o * 128 + k + 1) * 9 + t];
        uint32_t hp, lp;
        split_pack_s(v0, v1, hp, lp);
        g_wfh[i * 4 + m] = hp;
        g_wfl[i * 4 + m] = lp;
    }
}

// ---------------------------------------------------------------------------
// Weight prep: w_offset -> mma B-fragment order [t][ng(2)][k16(8)][lane][4]
// ---------------------------------------------------------------------------
__global__ void prep_wofrag_kernel(const float* __restrict__ wo) {
    int i = blockIdx.x * 256 + threadIdx.x;   // 0 .. 9*2*8*32-1
    if (i >= K2 * 2 * 8 * 32) return;
    int lane = i & 31;
    int kc8 = (i >> 5) & 7;
    int ng = (i >> 8) & 1;
    int t = i >> 9;
    #pragma unroll
    for (int m = 0; m < 4; m++) {
        int o = ng * 16 + (lane >> 2) + ((m >> 1) << 3);
        int k = kc8 * 16 + (lane & 3) * 2 + ((m & 1) << 3);
        float v0 = (o < 18) ? wo[(o * 128 + k) * 9 + t] : 0.f;
        float v1 = (o < 18) ? wo[(o * 128 + k + 1) * 9 + t] : 0.f;
        uint32_t hp, lp;
        split_pack_s(v0, v1, hp, lp);
        g_wofh[i * 4 + m] = hp;
        g_wofl[i * 4 + m] = lp;
    }
}

// ---------------------------------------------------------------------------
// FUSED kernel. Per CTA (128 px x full image):
//   Phase 1: offset conv for own 128 px (cp.async im2col pipeline, 18 halves)
//            -> offsets into smem offbuf [18][132].
//   Phase 2: deformable conv (half-K gather pipeline, 18 halves) -> out.
// SMEM (83232 B): A0[0,32K) A1[32K,64K) cw[64K,+4K) coff[68K,+4K)
//                 offbuf[72K, +9504)
// ---------------------------------------------------------------------------
#define DSM_A0 0u
#define DSM_A1 32768u
#define DSM_CW 65536u
#define DSM_CO 69632u
#define DSM_OFF 73728u
#define DSMEM_BYTES 83232

__global__ __launch_bounds__(256, 2) void fused_mma(float* __restrict__ out) {
    extern __shared__ char smem[];
    const uint32_t sb = smem_u32(smem);
    const int tid = threadIdx.x;
    const int lane = tid & 31;
    const int wid = tid >> 5;
    const int b = blockIdx.x >> 5;
    const int pix0 = (blockIdx.x & 31) * 128;

    float* offbuf = (float*)(smem + DSM_OFF);   // [ch][132]

    // ======================= Phase 1: offset conv =======================
    {
        float acc[4][4] = {};

        auto stage = [&](int hh) {
            int tap = hh >> 1;
            int c0 = (hh & 1) * 64;
            int ky = tap / 3 - 1, kx = tap % 3 - 1;
            uint32_t ab = sb + ((hh & 1) ? DSM_A1 : DSM_A0);
            #pragma unroll
            for (int q = 0; q < 8; q++) {
                int cid = tid + 256 * q;
                int p = cid >> 4, sub = cid & 15;
                int cc = sub & 7;
                int gp = pix0 + p;
                int y = (gp >> 6) + ky;
                int xx = (gp & 63) + kx;
                bool ok = ((unsigned)y < 64u) && ((unsigned)xx < 64u);
                const __nv_bfloat16* sp = (sub < 8 ? g_xbh : g_xbl)
                    + ((size_t)b * HW + (ok ? ((y << 6) + xx) : 0)) * 128
                    + c0 + cc * 8;
                uint32_t dst = ab + (uint32_t)p * 256u
                             + ((uint32_t)(cc ^ (p & 7)) << 4)
                             + (sub < 8 ? 0u : 128u);
                cp_async16(dst, sp, ok ? 16 : 0);
            }
        };

        stage(0);
        CP_COMMIT();

        for (int hh = 0; hh < 18; hh++) {
            CP_WAIT0();
            __syncthreads();
            if (hh + 1 < 18) { stage(hh + 1); CP_COMMIT(); }

            int tap = hh >> 1, half = hh & 1;
            uint32_t abu = sb + (half ? DSM_A1 : DSM_A0);
            #pragma unroll
            for (int kc = 0; kc < 4; kc++) {
                uint32_t ah[4], al[4];
                int mat = lane >> 3;
                int arow = wid * 16 + (lane & 7) + ((mat & 1) << 3);
                int kcol = kc * 16 + ((mat >> 1) << 3);
                uint32_t c = (uint32_t)(kcol >> 3);
                uint32_t aoff = (uint32_t)arow * 256u
                              + ((c ^ ((uint32_t)arow & 7u)) << 4);
                ldsm_x4(ah, abu + aoff);
                ldsm_x4(al, abu + aoff + 128);
                #pragma unroll
                for (int ng = 0; ng < 2; ng++) {
                    size_t fi = ((((size_t)tap * 2 + ng) * 8 + half * 4 + kc)
                                 * 32 + lane) * 4;
                    uint4 whf = *(const uint4*)(g_wofh + fi);
                    uint4 wlf = *(const uint4*)(g_wofl + fi);
                    uint32_t bh[4] = {whf.x, whf.y, whf.z, whf.w};
                    uint32_t bl[4] = {wlf.x, wlf.y, wlf.z, wlf.w};
                    mma_bf16(acc[ng * 2 + 0], ah, bh + 0);
                    mma_bf16(acc[ng * 2 + 1], ah, bh + 2);
                    mma_bf16(acc[ng * 2 + 0], al, bh + 0);
                    mma_bf16(acc[ng * 2 + 1], al, bh + 2);
                    mma_bf16(acc[ng * 2 + 0], ah, bl + 0);
                    mma_bf16(acc[ng * 2 + 1], ah, bl + 2);
                }
            }
        }
        __syncthreads();   // all phase-1 MMAs done before offbuf writes race reads

        int pl = wid * 16 + (lane >> 2);
        #pragma unroll
        for (int nt = 0; nt < 4; nt++) {
            int ch = nt * 8 + (lane & 3) * 2;
            if (ch < 18) {
                offbuf[ch * 132 + pl]            = acc[nt][0];
                offbuf[(ch + 1) * 132 + pl]      = acc[nt][1];
                offbuf[ch * 132 + pl + 8]        = acc[nt][2];
                offbuf[(ch + 1) * 132 + pl + 8]  = acc[nt][3];
            }
        }
        __syncthreads();
    }

    // ======================= Phase 2: deformable conv ====================
    const int wy = wid & 3;          // px group: 32 px
    const int wx = wid >> 2;         // out group: 64 o

    float* cwbuf = (float*)(smem + DSM_CW);   // [par][j*128+p]
    int* cobuf = (int*)(smem + DSM_CO);
    const float* xb = g_xt + (size_t)b * HW * C_IN;

    float acc[2][8][4] = {};

    auto tap_setup = [&](int tap) {
        if (tid < 128) {
            int p = tid;
            int par = tap & 1;
            int gp = pix0 + p;
            int h = gp >> 6, w = gp & 63;
            float dy = offbuf[(2 * tap) * 132 + p];
            float dx = offbuf[(2 * tap + 1) * 132 + p];
            float py = (float)(h - 1 + tap / 3) + dy;
            float px = (float)(w - 1 + tap % 3) + dx;
            float y0f = floorf(py), x0f = floorf(px);
            float fy = py - y0f, fx = px - x0f;
            #pragma unroll
            for (int j = 0; j < 4; j++) {
                float yf = y0f + (float)(j >> 1);
                float xf = x0f + (float)(j & 1);
                bool ok = (yf >= 0.f && yf < 64.f && xf >= 0.f && xf < 64.f);
                float wy_ = (j >> 1) ? fy : 1.f - fy;
                float wx_ = (j & 1) ? fx : 1.f - fx;
                cwbuf[par * 512 + j * 128 + p] = ok ? wy_ * wx_ : 0.f;
                int yi = (int)fminf(fmaxf(yf, 0.f), 63.f);
                int xi = (int)fminf(fmaxf(xf, 0.f), 63.f);
                cobuf[par * 512 + j * 128 + p] = ((yi << 6) + xi) << 7;
            }
        }
    };

    auto gather_half = [&](int hh2) {
        int par = (hh2 >> 1) & 1;
        int c0 = (hh2 & 1) * 64;
        char* ab = smem + ((hh2 & 1) ? DSM_A1 : DSM_A0);
        const float* cw = cwbuf + par * 512;
        const int* co = cobuf + par * 512;
        #pragma unroll 4
        for (int i = 0; i < 16; i++) {
            int p = wid * 16 + i;
            float w0 = cw[p], w1 = cw[128 + p];
            float w2 = cw[256 + p], w3 = cw[384 + p];
            int o0 = co[p], o1 = co[128 + p];
            int o2 = co[256 + p], o3 = co[384 + p];
            float vx = 0.f, vy = 0.f;
            const float* base = xb + c0 + 2 * lane;
            if (w0 != 0.f) { float2 t = *(const float2*)(base + o0); vx += w0 * t.x; vy += w0 * t.y; }
            if (w1 != 0.f) { float2 t = *(const float2*)(base + o1); vx += w1 * t.x; vy += w1 * t.y; }
            if (w2 != 0.f) { float2 t = *(const float2*)(base + o2); vx += w2 * t.x; vy += w2 * t.y; }
            if (w3 != 0.f) { float2 t = *(const float2*)(base + o3); vx += w3 * t.x; vy += w3 * t.y; }
            uint32_t hp, lp;
            split_pack(vx, vy, hp, lp);
            uint32_t sw = (uint32_t)p * 256u
                        + ((((uint32_t)lane >> 2) ^ ((uint32_t)p & 7u)) << 4)
                        + (((uint32_t)lane & 3u) << 2);
            *(uint32_t*)(ab + sw) = hp;
            *(uint32_t*)(ab + sw + 128) = lp;
        }
    };

    tap_setup(0);
    __syncthreads();
    gather_half(0);
    __syncthreads();

    for (int hh = 0; hh < 18; hh++) {
        int tap = hh >> 1;
        int half = hh & 1;

        if (half == 0 && tap + 1 < 9) tap_setup(tap + 1);
        if (hh + 1 < 18) gather_half(hh + 1);

        uint32_t abu = sb + (half ? DSM_A1 : DSM_A0);
        #pragma unroll
        for (int kc = 0; kc < 4; kc++) {
            uint32_t ah[2][4], al[2][4];
            #pragma unroll
            for (int mt = 0; mt < 2; mt++) {
                int mat = lane >> 3;
                int arow = wy * 32 + mt * 16 + (lane & 7) + ((mat & 1) << 3);
                int kcol = kc * 16 + ((mat >> 1) << 3);
                uint32_t c = (uint32_t)(kcol >> 3);
                uint32_t aoff = (uint32_t)arow * 256u
                              + ((c ^ ((uint32_t)arow & 7u)) << 4);
                ldsm_x4(ah[mt], abu + aoff);
                ldsm_x4(al[mt], abu + aoff + 128);
            }
            #pragma unroll
            for (int ng = 0; ng < 4; ng++) {
                int g = wx * 4 + ng;
                size_t fi = ((((size_t)tap * 8 + g) * 8 + half * 4 + kc) * 32
                             + lane) * 4;
                uint4 whf = *(const uint4*)(g_wfh + fi);
                uint4 wlf = *(const uint4*)(g_wfl + fi);
                uint32_t bh[4] = {whf.x, whf.y, whf.z, whf.w};
                uint32_t bl[4] = {wlf.x, wlf.y, wlf.z, wlf.w};
                #pragma unroll
                for (int mt = 0; mt < 2; mt++) {
                    mma_bf16(acc[mt][ng * 2 + 0], ah[mt], bh + 0);
                    mma_bf16(acc[mt][ng * 2 + 1], ah[mt], bh + 2);
                    mma_bf16(acc[mt][ng * 2 + 0], al[mt], bh + 0);
                    mma_bf16(acc[mt][ng * 2 + 1], al[mt], bh + 2);
                    mma_bf16(acc[mt][ng * 2 + 0], ah[mt], bl + 0);
                    mma_bf16(acc[mt][ng * 2 + 1], ah[mt], bl + 2);
                }
            }
        }
        __syncthreads();
    }

    // --- epilogue: c-frag -> out[b][o][px] ---
    float* ob = out + (size_t)b * 128 * HW;
    #pragma unroll
    for (int mt = 0; mt < 2; mt++) {
        int px0 = pix0 + wy * 32 + mt * 16 + (lane >> 2);
        #pragma unroll
        for (int nt = 0; nt < 8; nt++) {
            int o = wx * 64 + nt * 8 + (lane & 3) * 2;
            ob[(size_t)o * HW + px0]            = acc[mt][nt][0];
            ob[(size_t)(o + 1) * HW + px0]      = acc[mt][nt][1];
            ob[(size_t)o * HW + px0 + 8]        = acc[mt][nt][2];
            ob[(size_t)(o + 1) * HW + px0 + 8]  = acc[mt][nt][3];
        }
    }
}

// ---------------------------------------------------------------------------
extern "C" void kernel_launch(void* const* d_in, const int* in_sizes, int n_in,
                              void* d_out, int out_size) {
    const float* x  = (const float*)d_in[0];
    const float* wo = (const float*)d_in[1];   // w_offset
    const float* wc = (const float*)d_in[2];   // w_conv
    float* out = (float*)d_out;

    static bool attr_set = false;
    if (!attr_set) {
        cudaFuncSetAttribute(fused_mma,
                             cudaFuncAttributeMaxDynamicSharedMemorySize,
                             DSMEM_BYTES);
        attr_set = true;
    }

    dim3 tpb(32, 8);
    transpose_x_kernel<<<dim3(HW / 32, C_IN / 32, Bn), tpb>>>(x);
    prep_wfrag_kernel<<<(K2 * 8 * 8 * 32 + 255) / 256, 256>>>(wc);
    prep_wofrag_kernel<<<(K2 * 2 * 8 * 32 + 255) / 256, 256>>>(wo);
    fused_mma<<<Bn * (HW / 128), 256, DSMEM_BYTES>>>(out);
}